// round 7
// baseline (speedup 1.0000x reference)
#include <cuda_runtime.h>
#include <cuda_bf16.h>
#include <cstdint>

// ---------------------------------------------------------------------------
// GraphSAGE, mma.sync bf16 hi/lo (3-product fp32-accurate).
// gemm_k: CTA = 256 thr (8 warps, 4m x 2n), tile M=128 x N=128, warp 32x64.
// K=256 in 8 chunks of 32; A gathered->regs->split->SMEM, W via cp.async,
// both double-buffered. SMEM 80 KB -> 2 CTAs/SM.
// fc_k: fused row-L2-normalize + FC.
// ---------------------------------------------------------------------------

#define B_ROOT 16384
#define R1     49152
#define RSA    40            // chunk tile row stride (bf16), k32 + pad 8
#define RSW    264           // fc_k full-K row stride

// gemm_k smem (bytes)
#define GPL    10240                     // one plane: 128 x 40 x 2B
#define GA(b)  ((b) * 20480)             // A buf: hi +0, lo +GPL
#define GW(b)  (40960 + (b) * 20480)     // W buf: hi +0, lo +GPL
#define G_SMEM 81920
// fc_k smem offsets
#define F_AH   0
#define F_AL   33792
#define F_WH   67584
#define F_WL   135168
#define F_SMEM 202752

// ---------------- scratch ----------------------------------------------------
__device__ float g_F0[B_ROOT * 256];
__device__ float g_F1[R1 * 256];
__device__ float g_G [B_ROOT * 256];
__device__ __nv_bfloat16 g_whi[5 * 32768];
__device__ __nv_bfloat16 g_wlo[5 * 32768];

// ---------------- helpers ----------------------------------------------------
__device__ __forceinline__ uint32_t smem_u32(const void* p) {
    uint32_t a;
    asm("{ .reg .u64 t; cvta.to.shared.u64 t, %1; cvt.u32.u64 %0, t; }"
        : "=r"(a) : "l"(p));
    return a;
}
__device__ __forceinline__ void split2(float a, float b, uint32_t& h, uint32_t& l) {
    __nv_bfloat16 ah = __float2bfloat16_rn(a), bh = __float2bfloat16_rn(b);
    __nv_bfloat16 al = __float2bfloat16_rn(a - __bfloat162float(ah));
    __nv_bfloat16 bl = __float2bfloat16_rn(b - __bfloat162float(bh));
    __nv_bfloat162 ph = __halves2bfloat162(ah, bh);
    __nv_bfloat162 pl = __halves2bfloat162(al, bl);
    h = *reinterpret_cast<uint32_t*>(&ph);
    l = *reinterpret_cast<uint32_t*>(&pl);
}
__device__ __forceinline__ void split8(const float* v, uint4& h4, uint4& l4) {
    uint32_t h[4], l[4];
#pragma unroll
    for (int i = 0; i < 4; ++i) split2(v[2 * i], v[2 * i + 1], h[i], l[i]);
    h4 = make_uint4(h[0], h[1], h[2], h[3]);
    l4 = make_uint4(l[0], l[1], l[2], l[3]);
}
__device__ __forceinline__ void mma16816(float* d, const uint32_t* a,
                                         uint32_t b0, uint32_t b1) {
    asm volatile(
        "mma.sync.aligned.m16n8k16.row.col.f32.bf16.bf16.f32 "
        "{%0,%1,%2,%3}, {%4,%5,%6,%7}, {%8,%9}, {%0,%1,%2,%3};"
        : "+f"(d[0]), "+f"(d[1]), "+f"(d[2]), "+f"(d[3])
        : "r"(a[0]), "r"(a[1]), "r"(a[2]), "r"(a[3]), "r"(b0), "r"(b1));
}
__device__ __forceinline__ void ldmx4(uint32_t* r, uint32_t a) {
    asm volatile("ldmatrix.sync.aligned.m8n8.x4.shared.b16 {%0,%1,%2,%3}, [%4];"
                 : "=r"(r[0]), "=r"(r[1]), "=r"(r[2]), "=r"(r[3]) : "r"(a));
}
__device__ __forceinline__ void cp16(uint32_t dst, const void* src) {
    asm volatile("cp.async.cg.shared.global [%0], [%1], 16;" :: "r"(dst), "l"(src));
}
#define CP_COMMIT() asm volatile("cp.async.commit_group;" ::: "memory")
#define CP_WAIT0()  asm volatile("cp.async.wait_group 0;"  ::: "memory")

// ---------------- weight pre-split --------------------------------------------
__global__ void conv_w(const float* __restrict__ a, const float* __restrict__ b,
                       const float* __restrict__ c, const float* __restrict__ d,
                       const float* __restrict__ e,
                       __nv_bfloat16* __restrict__ hi, __nv_bfloat16* __restrict__ lo) {
    int t = blockIdx.x * blockDim.x + threadIdx.x;
    const float* src[5] = {a, b, c, d, e};
    float x = src[t >> 15][t & 32767];
    __nv_bfloat16 h = __float2bfloat16_rn(x);
    hi[t] = h;
    lo[t] = __float2bfloat16_rn(x - __bfloat162float(h));
}

// ---------------- layer GEMM ---------------------------------------------------
// C[m0+m, col_off+n] = relu( rowop(A)[m] . W[n] + bias[n] ),  W: [128,256] hi/lo
// GATHER: 0 = A[idx[m]], 1 = mean_{j<KF} A[idx[m*KF+j]], 2 = A[m], 3 = mean3 A[3m+j]
template <int GATHER, int KF>
__global__ void __launch_bounds__(256, 2)
gemm_k(const float* __restrict__ A, const int* __restrict__ idx,
       const __nv_bfloat16* __restrict__ w_hi, const __nv_bfloat16* __restrict__ w_lo,
       const float* __restrict__ bias,
       float* __restrict__ C, int ldc, int col_off)
{
    extern __shared__ char smem[];
    const uint32_t sb = smem_u32(smem);
    const int tid = threadIdx.x, lane = tid & 31, wid = tid >> 5;
    const int wm = wid >> 1, wn = wid & 1;            // 4m x 2n, warp 32x64
    const int lr = lane >> 2, lc = (lane & 3) * 2;
    const int g  = lane >> 3, lm = lane & 7;
    const int aro = ((g & 1) << 3) + lm, aco = (g >> 1) << 3;
    const int bro = ((g >> 1) << 3) + lm, bco = (g & 1) << 3;
    const int m0 = blockIdx.x * 128;
    const int r  = tid >> 1, cq = (tid & 1) * 16;     // A loader: row, col base

    // per-chunk W staging: 1024 cp16 across 256 threads = 4 each
    auto ISSUE_W = [&](int ch, int buf) {
        const int kb = ch * 32;
#pragma unroll
        for (int i = 0; i < 4; ++i) {
            int o = tid + i * 256;
            int plane = o >> 9, ix = o & 511;
            int row = ix >> 2, c8 = (ix & 3) * 8;
            const __nv_bfloat16* src =
                (plane ? w_lo : w_hi) + (size_t)row * 256 + kb + c8;
            cp16(sb + GW(buf) + (plane ? GPL : 0)
                 + (uint32_t)(row * RSA + c8) * 2, src);
        }
    };

    int rows[KF];
    if (GATHER == 0)      rows[0] = idx[m0 + r];
    else if (GATHER == 1) {
#pragma unroll
        for (int j = 0; j < KF; ++j) rows[j] = idx[(size_t)(m0 + r) * KF + j];
    } else if (GATHER == 2) rows[0] = m0 + r;
    else {
#pragma unroll
        for (int j = 0; j < KF; ++j) rows[j] = (m0 + r) * 3 + j;
    }

    float v[16];
    auto PREF = [&](int ch) {
        const int kb = ch * 32;
#pragma unroll
        for (int i = 0; i < 16; ++i) v[i] = 0.f;
#pragma unroll
        for (int j = 0; j < KF; ++j) {
            const float4* p = (const float4*)(A + (size_t)rows[j] * 256 + kb + cq);
#pragma unroll
            for (int q = 0; q < 4; ++q) {
                float4 f = __ldg(p + q);
                v[q * 4 + 0] += f.x; v[q * 4 + 1] += f.y;
                v[q * 4 + 2] += f.z; v[q * 4 + 3] += f.w;
            }
        }
    };
    auto STORE = [&](int buf) {
        const float s = 1.0f / (float)KF;
        float w[16];
#pragma unroll
        for (int i = 0; i < 16; ++i) w[i] = v[i] * s;
        uint4 h0, l0, h1, l1;
        split8(w, h0, l0);
        split8(w + 8, h1, l1);
        char* base = smem + GA(buf) + (size_t)(r * RSA + cq) * 2;
        *(uint4*)(base)             = h0;
        *(uint4*)(base + 16)        = h1;
        *(uint4*)(base + GPL)       = l0;
        *(uint4*)(base + GPL + 16)  = l1;
    };

    float d[2][8][4];
#pragma unroll
    for (int i = 0; i < 2; ++i)
#pragma unroll
        for (int j = 0; j < 8; ++j)
#pragma unroll
            for (int k = 0; k < 4; ++k) d[i][j][k] = 0.f;

    ISSUE_W(0, 0);
    CP_COMMIT();
    PREF(0);
    STORE(0);
    CP_WAIT0();
    __syncthreads();

#pragma unroll
    for (int ch = 0; ch < 8; ++ch) {
        const int cb = ch & 1, nb = cb ^ 1;
        if (ch < 7) {
            ISSUE_W(ch + 1, nb);
            CP_COMMIT();
            PREF(ch + 1);            // gather LDGs fly under the MMA burst
        }
        const uint32_t aH = sb + GA(cb), aL = aH + GPL;
        const uint32_t wH = sb + GW(cb), wL = wH + GPL;
#pragma unroll
        for (int ks = 0; ks < 2; ++ks) {
            uint32_t ah[2][4], al[2][4];
#pragma unroll
            for (int mi = 0; mi < 2; ++mi) {
                uint32_t ad = (uint32_t)((wm * 32 + mi * 16 + aro) * RSA
                                         + ks * 16 + aco) * 2;
                ldmx4(ah[mi], aH + ad);
                ldmx4(al[mi], aL + ad);
            }
#pragma unroll
            for (int nip = 0; nip < 4; ++nip) {
                uint32_t bd = (uint32_t)((wn * 64 + nip * 16 + bro) * RSA
                                         + ks * 16 + bco) * 2;
                uint32_t th[4], tl[4];
                ldmx4(th, wH + bd);
                ldmx4(tl, wL + bd);
#pragma unroll
                for (int sub = 0; sub < 2; ++sub) {
                    const int ni = 2 * nip + sub;
                    const uint32_t bh0 = th[2 * sub], bh1 = th[2 * sub + 1];
                    const uint32_t bl0 = tl[2 * sub], bl1 = tl[2 * sub + 1];
#pragma unroll
                    for (int mi = 0; mi < 2; ++mi) {
                        mma16816(d[mi][ni], ah[mi], bh0, bh1);
                        mma16816(d[mi][ni], ah[mi], bl0, bl1);
                        mma16816(d[mi][ni], al[mi], bh0, bh1);
                    }
                }
            }
        }
        if (ch < 7) {
            STORE(nb);
            CP_WAIT0();
        }
        __syncthreads();
    }

    // epilogue: bias + relu
#pragma unroll
    for (int mi = 0; mi < 2; ++mi) {
        const int row = m0 + wm * 32 + mi * 16 + lr;
#pragma unroll
        for (int ni = 0; ni < 8; ++ni) {
            const int col = wn * 64 + ni * 8 + lc;
            const float b0 = __ldg(&bias[col]), b1 = __ldg(&bias[col + 1]);
            *(float2*)(C + (size_t)row * ldc + col_off + col) =
                make_float2(fmaxf(d[mi][ni][0] + b0, 0.f),
                            fmaxf(d[mi][ni][1] + b1, 0.f));
            *(float2*)(C + (size_t)(row + 8) * ldc + col_off + col) =
                make_float2(fmaxf(d[mi][ni][2] + b0, 0.f),
                            fmaxf(d[mi][ni][3] + b1, 0.f));
        }
    }
}

// ---------------- final: row L2-normalize + FC ---------------------------------
__global__ void __launch_bounds__(256)
fc_k(const float* __restrict__ Gm,
     const __nv_bfloat16* __restrict__ w_hi, const __nv_bfloat16* __restrict__ w_lo,
     const float* __restrict__ bias, float* __restrict__ C)
{
    extern __shared__ char smem[];
    const uint32_t sb = smem_u32(smem);
    const int tid = threadIdx.x, lane = tid & 31, wid = tid >> 5;
    const int wm = wid >> 2, wn = wid & 3;
    const int lr = lane >> 2, lc = (lane & 3) * 2;
    const int g  = lane >> 3, lm = lane & 7;
    const int aro = ((g & 1) << 3) + lm, aco = (g >> 1) << 3;
    const int bro = ((g >> 1) << 3) + lm, bco = (g & 1) << 3;
    const int m0 = blockIdx.x * 64;
    const int r  = tid >> 2, c0 = (tid & 3) * 64;

#pragma unroll
    for (int i = 0; i < 32; ++i) {
        int o = tid + i * 256;
        int plane = o >> 12, ix = o & 4095;
        int row = ix >> 5, c8 = (ix & 31) * 8;
        const __nv_bfloat16* src = (plane ? w_lo : w_hi) + (size_t)row * 256 + c8;
        cp16(sb + (plane ? F_WL : F_WH) + (uint32_t)(row * RSW + c8) * 2, src);
    }
    CP_COMMIT();

    float v[64];
    float ss = 0.f;
    const float4* p = (const float4*)(Gm + (size_t)(m0 + r) * 256 + c0);
#pragma unroll
    for (int q = 0; q < 16; ++q) {
        float4 f = __ldg(p + q);
        v[q * 4 + 0] = f.x; v[q * 4 + 1] = f.y;
        v[q * 4 + 2] = f.z; v[q * 4 + 3] = f.w;
        ss += f.x * f.x + f.y * f.y + f.z * f.z + f.w * f.w;
    }
    ss += __shfl_xor_sync(0xffffffffu, ss, 1);
    ss += __shfl_xor_sync(0xffffffffu, ss, 2);
    const float sc = 1.0f / fmaxf(sqrtf(ss), 1e-12f);
#pragma unroll
    for (int i = 0; i < 64; ++i) v[i] *= sc;
#pragma unroll
    for (int q = 0; q < 8; ++q) {
        uint4 h4, l4;
        split8(v + q * 8, h4, l4);
        size_t off = (size_t)(r * RSW + c0 + q * 8) * 2;
        *(uint4*)(smem + F_AH + off) = h4;
        *(uint4*)(smem + F_AL + off) = l4;
    }
    CP_WAIT0();
    __syncthreads();

    float d[2][4][4];
#pragma unroll
    for (int i = 0; i < 2; ++i)
#pragma unroll
        for (int j = 0; j < 4; ++j)
#pragma unroll
            for (int k = 0; k < 4; ++k) d[i][j][k] = 0.f;

#pragma unroll
    for (int ks = 0; ks < 16; ++ks) {
        uint32_t ah[2][4], al[2][4];
#pragma unroll
        for (int mi = 0; mi < 2; ++mi) {
            uint32_t ad = (uint32_t)((wm * 32 + mi * 16 + aro) * RSW
                                     + ks * 16 + aco) * 2;
            ldmx4(ah[mi], sb + F_AH + ad);
            ldmx4(al[mi], sb + F_AL + ad);
        }
        uint32_t bh[4][2], bl[4][2];
#pragma unroll
        for (int nip = 0; nip < 2; ++nip) {
            uint32_t bd = (uint32_t)((wn * 32 + nip * 16 + bro) * RSW
                                     + ks * 16 + bco) * 2;
            uint32_t t4[4];
            ldmx4(t4, sb + F_WH + bd);
            bh[2 * nip][0] = t4[0]; bh[2 * nip][1] = t4[1];
            bh[2 * nip + 1][0] = t4[2]; bh[2 * nip + 1][1] = t4[3];
            ldmx4(t4, sb + F_WL + bd);
            bl[2 * nip][0] = t4[0]; bl[2 * nip][1] = t4[1];
            bl[2 * nip + 1][0] = t4[2]; bl[2 * nip + 1][1] = t4[3];
        }
#pragma unroll
        for (int ni = 0; ni < 4; ++ni)
#pragma unroll
            for (int mi = 0; mi < 2; ++mi) {
                mma16816(d[mi][ni], ah[mi], bh[ni][0], bh[ni][1]);
                mma16816(d[mi][ni], ah[mi], bl[ni][0], bl[ni][1]);
                mma16816(d[mi][ni], al[mi], bh[ni][0], bh[ni][1]);
            }
    }

#pragma unroll
    for (int mi = 0; mi < 2; ++mi) {
        const int row = m0 + wm * 32 + mi * 16 + lr;
#pragma unroll
        for (int ni = 0; ni < 4; ++ni) {
            const int col = wn * 32 + ni * 8 + lc;
            const float b0 = __ldg(&bias[col]), b1 = __ldg(&bias[col + 1]);
            *(float2*)(C + (size_t)row * 128 + col) =
                make_float2(d[mi][ni][0] + b0, d[mi][ni][1] + b1);
            *(float2*)(C + (size_t)(row + 8) * 128 + col) =
                make_float2(d[mi][ni][2] + b0, d[mi][ni][3] + b1);
        }
    }
}

// ---------------------------------------------------------------------------
extern "C" void kernel_launch(void* const* d_in, const int* in_sizes, int n_in,
                              void* d_out, int out_size)
{
    const float* emb      = (const float*)d_in[0];
    const float* w_self0  = (const float*)d_in[1];
    const float* b_self0  = (const float*)d_in[2];
    const float* w_neigh0 = (const float*)d_in[3];
    const float* b_neigh0 = (const float*)d_in[4];
    const float* w_self1  = (const float*)d_in[5];
    const float* b_self1  = (const float*)d_in[6];
    const float* w_neigh1 = (const float*)d_in[7];
    const float* b_neigh1 = (const float*)d_in[8];
    const float* fc_w     = (const float*)d_in[9];
    const float* fc_b     = (const float*)d_in[10];
    const int*   nodeids  = (const int*)d_in[11];
    const int*   neigh1   = (const int*)d_in[12];
    const int*   neigh2   = (const int*)d_in[13];
    float*       out      = (float*)d_out;

    __nv_bfloat16 *WHI, *WLO;
    float *F0, *F1, *Gg;
    cudaGetSymbolAddress((void**)&WHI, g_whi);
    cudaGetSymbolAddress((void**)&WLO, g_wlo);
    cudaGetSymbolAddress((void**)&F0, g_F0);
    cudaGetSymbolAddress((void**)&F1, g_F1);
    cudaGetSymbolAddress((void**)&Gg, g_G);

    cudaFuncSetAttribute(gemm_k<0,1>, cudaFuncAttributeMaxDynamicSharedMemorySize, G_SMEM);
    cudaFuncSetAttribute(gemm_k<1,3>, cudaFuncAttributeMaxDynamicSharedMemorySize, G_SMEM);
    cudaFuncSetAttribute(gemm_k<1,5>, cudaFuncAttributeMaxDynamicSharedMemorySize, G_SMEM);
    cudaFuncSetAttribute(gemm_k<2,1>, cudaFuncAttributeMaxDynamicSharedMemorySize, G_SMEM);
    cudaFuncSetAttribute(gemm_k<3,3>, cudaFuncAttributeMaxDynamicSharedMemorySize, G_SMEM);
    cudaFuncSetAttribute(fc_k,        cudaFuncAttributeMaxDynamicSharedMemorySize, F_SMEM);

    conv_w<<<640, 256>>>(w_self0, w_neigh0, w_self1, w_neigh1, fc_w, WHI, WLO);

    // layer 0 (both readers of emb[neigh1] back-to-back for L2 reuse)
    gemm_k<0,1><<<B_ROOT/128, 256, G_SMEM>>>(emb, nodeids, WHI, WLO,
                                             b_self0, F0, 256, 0);
    gemm_k<1,3><<<B_ROOT/128, 256, G_SMEM>>>(emb, neigh1, WHI + 32768, WLO + 32768,
                                             b_neigh0, F0, 256, 128);
    gemm_k<0,1><<<R1/128, 256, G_SMEM>>>(emb, neigh1, WHI, WLO,
                                         b_self0, F1, 256, 0);
    gemm_k<1,5><<<R1/128, 256, G_SMEM>>>(emb, neigh2, WHI + 32768, WLO + 32768,
                                         b_neigh0, F1, 256, 128);

    // layer 1
    gemm_k<2,1><<<B_ROOT/128, 256, G_SMEM>>>(F0, nullptr, WHI + 65536, WLO + 65536,
                                             b_self1, Gg, 256, 0);
    gemm_k<3,3><<<B_ROOT/128, 256, G_SMEM>>>(F1, nullptr, WHI + 98304, WLO + 98304,
                                             b_neigh1, Gg, 256, 128);

    // normalize + FC
    fc_k<<<B_ROOT/64, 256, F_SMEM>>>(Gg, WHI + 131072, WLO + 131072, fc_b, out);
}

// round 8
// speedup vs baseline: 1.1401x; 1.1401x over previous
#include <cuda_runtime.h>
#include <cuda_bf16.h>
#include <cstdint>

// ---------------------------------------------------------------------------
// GraphSAGE, mma.sync bf16 hi/lo (3-product fp32-accurate).
// gemm_body: CTA = 256 thr (8 warps, 2m x 4n), tile M=64 x N=128, K=256 in 4
// chunks of 64; A gathered->regs->split->SMEM, W per-chunk double-buffered
// via cp.async. SMEM 108 KB -> 2 CTAs/SM.
// Launch structure: layer0 (4 segments, 1 launch), layer1 (2 segments),
// fc_k (fused row-L2-normalize + FC). Segment dispatch by blockIdx range.
// ---------------------------------------------------------------------------

#define B_ROOT 16384
#define R1     49152
#define RSA    72            // chunk tile row stride (bf16 elems)
#define RSW    264           // fc_k full-K row stride

// gemm smem (bytes): A bufs then W bufs
#define GA(b)  ((b) * 18432)                 // A: hi +0, lo +9216
#define GW(b)  (36864 + (b) * 36864)         // W: hi +0, lo +18432
#define G_SMEM 110592
// fc_k smem offsets
#define F_AH   0
#define F_AL   33792
#define F_WH   67584
#define F_WL   135168
#define F_SMEM 202752

// ---------------- scratch ----------------------------------------------------
__device__ float g_F0[B_ROOT * 256];
__device__ float g_F1[R1 * 256];
__device__ float g_G [B_ROOT * 256];
__device__ __nv_bfloat16 g_whi[5 * 32768];
__device__ __nv_bfloat16 g_wlo[5 * 32768];

// ---------------- helpers ----------------------------------------------------
__device__ __forceinline__ uint32_t smem_u32(const void* p) {
    uint32_t a;
    asm("{ .reg .u64 t; cvta.to.shared.u64 t, %1; cvt.u32.u64 %0, t; }"
        : "=r"(a) : "l"(p));
    return a;
}
__device__ __forceinline__ void split2(float a, float b, uint32_t& h, uint32_t& l) {
    __nv_bfloat16 ah = __float2bfloat16_rn(a), bh = __float2bfloat16_rn(b);
    __nv_bfloat16 al = __float2bfloat16_rn(a - __bfloat162float(ah));
    __nv_bfloat16 bl = __float2bfloat16_rn(b - __bfloat162float(bh));
    __nv_bfloat162 ph = __halves2bfloat162(ah, bh);
    __nv_bfloat162 pl = __halves2bfloat162(al, bl);
    h = *reinterpret_cast<uint32_t*>(&ph);
    l = *reinterpret_cast<uint32_t*>(&pl);
}
__device__ __forceinline__ void split8(const float* v, uint4& h4, uint4& l4) {
    uint32_t h[4], l[4];
#pragma unroll
    for (int i = 0; i < 4; ++i) split2(v[2 * i], v[2 * i + 1], h[i], l[i]);
    h4 = make_uint4(h[0], h[1], h[2], h[3]);
    l4 = make_uint4(l[0], l[1], l[2], l[3]);
}
__device__ __forceinline__ void mma16816(float* d, const uint32_t* a,
                                         uint32_t b0, uint32_t b1) {
    asm volatile(
        "mma.sync.aligned.m16n8k16.row.col.f32.bf16.bf16.f32 "
        "{%0,%1,%2,%3}, {%4,%5,%6,%7}, {%8,%9}, {%0,%1,%2,%3};"
        : "+f"(d[0]), "+f"(d[1]), "+f"(d[2]), "+f"(d[3])
        : "r"(a[0]), "r"(a[1]), "r"(a[2]), "r"(a[3]), "r"(b0), "r"(b1));
}
__device__ __forceinline__ void ldmx4(uint32_t* r, uint32_t a) {
    asm volatile("ldmatrix.sync.aligned.m8n8.x4.shared.b16 {%0,%1,%2,%3}, [%4];"
                 : "=r"(r[0]), "=r"(r[1]), "=r"(r[2]), "=r"(r[3]) : "r"(a));
}
__device__ __forceinline__ void cp16(uint32_t dst, const void* src) {
    asm volatile("cp.async.cg.shared.global [%0], [%1], 16;" :: "r"(dst), "l"(src));
}
#define CP_COMMIT() asm volatile("cp.async.commit_group;" ::: "memory")
#define CP_WAIT0()  asm volatile("cp.async.wait_group 0;"  ::: "memory")

// ---------------- weight pre-split --------------------------------------------
__global__ void conv_w(const float* __restrict__ a, const float* __restrict__ b,
                       const float* __restrict__ c, const float* __restrict__ d,
                       const float* __restrict__ e,
                       __nv_bfloat16* __restrict__ hi, __nv_bfloat16* __restrict__ lo) {
    int t = blockIdx.x * blockDim.x + threadIdx.x;
    const float* src[5] = {a, b, c, d, e};
    float x = src[t >> 15][t & 32767];
    __nv_bfloat16 h = __float2bfloat16_rn(x);
    hi[t] = h;
    lo[t] = __float2bfloat16_rn(x - __bfloat162float(h));
}

// ---------------- GEMM body (device function) ----------------------------------
// C[m0+m, col_off+n] = relu( rowop(A)[m] . W[n] + bias[n] ),  W: [128,256] hi/lo
// GATHER: 0 = A[idx[m]], 1 = mean_{j<KF} A[idx[m*KF+j]], 2 = A[m], 3 = mean3 A[3m+j]
template <int GATHER, int KF>
__device__ __forceinline__ void
gemm_body(char* smem, const float* __restrict__ A, const int* __restrict__ idx,
          const __nv_bfloat16* __restrict__ w_hi, const __nv_bfloat16* __restrict__ w_lo,
          const float* __restrict__ bias,
          float* __restrict__ C, int ldc, int col_off, int m0)
{
    const uint32_t sb = smem_u32(smem);
    const int tid = threadIdx.x, lane = tid & 31, wid = tid >> 5;
    const int wm = wid >> 2, wn = wid & 3;
    const int lr = lane >> 2, lc = (lane & 3) * 2;
    const int g  = lane >> 3, lm = lane & 7;
    const int aro = ((g & 1) << 3) + lm, aco = (g >> 1) << 3;
    const int bro = ((g >> 1) << 3) + lm, bco = (g & 1) << 3;
    const int r  = tid >> 2, cq = (tid & 3) * 16;

    auto ISSUE_W = [&](int ch, int buf) {
        const int kb = ch * 64;
#pragma unroll
        for (int i = 0; i < 8; ++i) {
            int o = tid + i * 256;
            int plane = o >> 10, ix = o & 1023;
            int row = ix >> 3, c8 = (ix & 7) * 8;
            const __nv_bfloat16* src =
                (plane ? w_lo : w_hi) + (size_t)row * 256 + kb + c8;
            cp16(sb + GW(buf) + (plane ? 18432 : 0)
                 + (uint32_t)(row * RSA + c8) * 2, src);
        }
    };

    int rows[KF];
    if (GATHER == 0)      rows[0] = idx[m0 + r];
    else if (GATHER == 1) {
#pragma unroll
        for (int j = 0; j < KF; ++j) rows[j] = idx[(size_t)(m0 + r) * KF + j];
    } else if (GATHER == 2) rows[0] = m0 + r;
    else {
#pragma unroll
        for (int j = 0; j < KF; ++j) rows[j] = (m0 + r) * 3 + j;
    }

    float v[16];
    auto PREF = [&](int ch) {
        const int kb = ch * 64;
#pragma unroll
        for (int i = 0; i < 16; ++i) v[i] = 0.f;
#pragma unroll
        for (int j = 0; j < KF; ++j) {
            const float4* p = (const float4*)(A + (size_t)rows[j] * 256 + kb + cq);
#pragma unroll
            for (int q = 0; q < 4; ++q) {
                float4 f = __ldg(p + q);
                v[q * 4 + 0] += f.x; v[q * 4 + 1] += f.y;
                v[q * 4 + 2] += f.z; v[q * 4 + 3] += f.w;
            }
        }
    };
    auto STORE = [&](int buf) {
        const float s = 1.0f / (float)KF;
        float w[16];
#pragma unroll
        for (int i = 0; i < 16; ++i) w[i] = v[i] * s;
        uint4 h0, l0, h1, l1;
        split8(w, h0, l0);
        split8(w + 8, h1, l1);
        char* base = smem + GA(buf) + (size_t)(r * RSA + cq) * 2;
        *(uint4*)(base)              = h0;
        *(uint4*)(base + 16)         = h1;
        *(uint4*)(base + 9216)       = l0;
        *(uint4*)(base + 9216 + 16)  = l1;
    };

    float d[2][4][4];
#pragma unroll
    for (int i = 0; i < 2; ++i)
#pragma unroll
        for (int j = 0; j < 4; ++j)
#pragma unroll
            for (int k = 0; k < 4; ++k) d[i][j][k] = 0.f;

    ISSUE_W(0, 0);
    CP_COMMIT();
    PREF(0);
    STORE(0);
    CP_WAIT0();
    __syncthreads();

#pragma unroll
    for (int ch = 0; ch < 4; ++ch) {
        const int cb = ch & 1, nb = cb ^ 1;
        if (ch < 3) {
            ISSUE_W(ch + 1, nb);
            CP_COMMIT();
            PREF(ch + 1);           // gather LDGs fly under the MMA burst
        }
        const uint32_t aH = sb + GA(cb), aL = aH + 9216;
        const uint32_t wH = sb + GW(cb), wL = wH + 18432;
#pragma unroll
        for (int ks = 0; ks < 4; ++ks) {
            uint32_t ah[2][4], al[2][4];
#pragma unroll
            for (int mi = 0; mi < 2; ++mi) {
                uint32_t ad = (uint32_t)((wm * 32 + mi * 16 + aro) * RSA
                                         + ks * 16 + aco) * 2;
                ldmx4(ah[mi], aH + ad);
                ldmx4(al[mi], aL + ad);
            }
            uint32_t bh[4][2], bl[4][2];
#pragma unroll
            for (int nip = 0; nip < 2; ++nip) {
                uint32_t bd = (uint32_t)((wn * 32 + nip * 16 + bro) * RSA
                                         + ks * 16 + bco) * 2;
                uint32_t t4[4];
                ldmx4(t4, wH + bd);
                bh[2 * nip][0] = t4[0]; bh[2 * nip][1] = t4[1];
                bh[2 * nip + 1][0] = t4[2]; bh[2 * nip + 1][1] = t4[3];
                ldmx4(t4, wL + bd);
                bl[2 * nip][0] = t4[0]; bl[2 * nip][1] = t4[1];
                bl[2 * nip + 1][0] = t4[2]; bl[2 * nip + 1][1] = t4[3];
            }
#pragma unroll
            for (int ni = 0; ni < 4; ++ni)
#pragma unroll
                for (int mi = 0; mi < 2; ++mi) {
                    mma16816(d[mi][ni], ah[mi], bh[ni][0], bh[ni][1]);
                    mma16816(d[mi][ni], ah[mi], bl[ni][0], bl[ni][1]);
                    mma16816(d[mi][ni], al[mi], bh[ni][0], bh[ni][1]);
                }
        }
        if (ch < 3) {
            STORE(nb);
            CP_WAIT0();
        }
        __syncthreads();
    }

    // epilogue: bias + relu
#pragma unroll
    for (int mi = 0; mi < 2; ++mi) {
        const int row = m0 + wm * 32 + mi * 16 + lr;
#pragma unroll
        for (int ni = 0; ni < 4; ++ni) {
            const int col = wn * 32 + ni * 8 + lc;
            const float b0 = __ldg(&bias[col]), b1 = __ldg(&bias[col + 1]);
            *(float2*)(C + (size_t)row * ldc + col_off + col) =
                make_float2(fmaxf(d[mi][ni][0] + b0, 0.f),
                            fmaxf(d[mi][ni][1] + b1, 0.f));
            *(float2*)(C + (size_t)(row + 8) * ldc + col_off + col) =
                make_float2(fmaxf(d[mi][ni][2] + b0, 0.f),
                            fmaxf(d[mi][ni][3] + b1, 0.f));
        }
    }
}

// ---------------- layer 0: 4 segments, one launch -------------------------------
// bid [0,256)    : F0 self  = emb[nodeids]        @ Ws0
// bid [256,512)  : F0 neigh = mean3 emb[neigh1]   @ Wn0
// bid [512,1280) : F1 self  = emb[neigh1]         @ Ws0
// bid [1280,2048): F1 neigh = mean5 emb[neigh2]   @ Wn0
__global__ void __launch_bounds__(256, 2)
layer0_k(const float* __restrict__ emb,
         const int* __restrict__ nodeids, const int* __restrict__ neigh1,
         const int* __restrict__ neigh2,
         const __nv_bfloat16* __restrict__ whi, const __nv_bfloat16* __restrict__ wlo,
         const float* __restrict__ bs0, const float* __restrict__ bn0,
         float* __restrict__ F0, float* __restrict__ F1)
{
    extern __shared__ char smem[];
    const int bid = blockIdx.x;
    if (bid < 256) {
        gemm_body<0, 1>(smem, emb, nodeids, whi, wlo, bs0, F0, 256, 0, bid * 64);
    } else if (bid < 512) {
        gemm_body<1, 3>(smem, emb, neigh1, whi + 32768, wlo + 32768, bn0,
                        F0, 256, 128, (bid - 256) * 64);
    } else if (bid < 1280) {
        gemm_body<0, 1>(smem, emb, neigh1, whi, wlo, bs0,
                        F1, 256, 0, (bid - 512) * 64);
    } else {
        gemm_body<1, 5>(smem, emb, neigh2, whi + 32768, wlo + 32768, bn0,
                        F1, 256, 128, (bid - 1280) * 64);
    }
}

// ---------------- layer 1: 2 segments, one launch -------------------------------
__global__ void __launch_bounds__(256, 2)
layer1_k(const float* __restrict__ F0, const float* __restrict__ F1,
         const __nv_bfloat16* __restrict__ whi, const __nv_bfloat16* __restrict__ wlo,
         const float* __restrict__ bs1, const float* __restrict__ bn1,
         float* __restrict__ G)
{
    extern __shared__ char smem[];
    const int bid = blockIdx.x;
    if (bid < 256) {
        gemm_body<2, 1>(smem, F0, nullptr, whi + 65536, wlo + 65536, bs1,
                        G, 256, 0, bid * 64);
    } else {
        gemm_body<3, 3>(smem, F1, nullptr, whi + 98304, wlo + 98304, bn1,
                        G, 256, 128, (bid - 256) * 64);
    }
}

// ---------------- final: row L2-normalize + FC ---------------------------------
__global__ void __launch_bounds__(256)
fc_k(const float* __restrict__ Gm,
     const __nv_bfloat16* __restrict__ w_hi, const __nv_bfloat16* __restrict__ w_lo,
     const float* __restrict__ bias, float* __restrict__ C)
{
    extern __shared__ char smem[];
    const uint32_t sb = smem_u32(smem);
    const int tid = threadIdx.x, lane = tid & 31, wid = tid >> 5;
    const int wm = wid >> 2, wn = wid & 3;
    const int lr = lane >> 2, lc = (lane & 3) * 2;
    const int g  = lane >> 3, lm = lane & 7;
    const int aro = ((g & 1) << 3) + lm, aco = (g >> 1) << 3;
    const int bro = ((g >> 1) << 3) + lm, bco = (g & 1) << 3;
    const int m0 = blockIdx.x * 64;
    const int r  = tid >> 2, c0 = (tid & 3) * 64;

#pragma unroll
    for (int i = 0; i < 32; ++i) {
        int o = tid + i * 256;
        int plane = o >> 12, ix = o & 4095;
        int row = ix >> 5, c8 = (ix & 31) * 8;
        const __nv_bfloat16* src = (plane ? w_lo : w_hi) + (size_t)row * 256 + c8;
        cp16(sb + (plane ? F_WL : F_WH) + (uint32_t)(row * RSW + c8) * 2, src);
    }
    CP_COMMIT();

    float v[64];
    float ss = 0.f;
    const float4* p = (const float4*)(Gm + (size_t)(m0 + r) * 256 + c0);
#pragma unroll
    for (int q = 0; q < 16; ++q) {
        float4 f = __ldg(p + q);
        v[q * 4 + 0] = f.x; v[q * 4 + 1] = f.y;
        v[q * 4 + 2] = f.z; v[q * 4 + 3] = f.w;
        ss += f.x * f.x + f.y * f.y + f.z * f.z + f.w * f.w;
    }
    ss += __shfl_xor_sync(0xffffffffu, ss, 1);
    ss += __shfl_xor_sync(0xffffffffu, ss, 2);
    const float sc = 1.0f / fmaxf(sqrtf(ss), 1e-12f);
#pragma unroll
    for (int i = 0; i < 64; ++i) v[i] *= sc;
#pragma unroll
    for (int q = 0; q < 8; ++q) {
        uint4 h4, l4;
        split8(v + q * 8, h4, l4);
        size_t off = (size_t)(r * RSW + c0 + q * 8) * 2;
        *(uint4*)(smem + F_AH + off) = h4;
        *(uint4*)(smem + F_AL + off) = l4;
    }
    CP_WAIT0();
    __syncthreads();

    float d[2][4][4];
#pragma unroll
    for (int i = 0; i < 2; ++i)
#pragma unroll
        for (int j = 0; j < 4; ++j)
#pragma unroll
            for (int k = 0; k < 4; ++k) d[i][j][k] = 0.f;

#pragma unroll
    for (int ks = 0; ks < 16; ++ks) {
        uint32_t ah[2][4], al[2][4];
#pragma unroll
        for (int mi = 0; mi < 2; ++mi) {
            uint32_t ad = (uint32_t)((wm * 32 + mi * 16 + aro) * RSW
                                     + ks * 16 + aco) * 2;
            ldmx4(ah[mi], sb + F_AH + ad);
            ldmx4(al[mi], sb + F_AL + ad);
        }
        uint32_t bh[4][2], bl[4][2];
#pragma unroll
        for (int nip = 0; nip < 2; ++nip) {
            uint32_t bd = (uint32_t)((wn * 32 + nip * 16 + bro) * RSW
                                     + ks * 16 + bco) * 2;
            uint32_t t4[4];
            ldmx4(t4, sb + F_WH + bd);
            bh[2 * nip][0] = t4[0]; bh[2 * nip][1] = t4[1];
            bh[2 * nip + 1][0] = t4[2]; bh[2 * nip + 1][1] = t4[3];
            ldmx4(t4, sb + F_WL + bd);
            bl[2 * nip][0] = t4[0]; bl[2 * nip][1] = t4[1];
            bl[2 * nip + 1][0] = t4[2]; bl[2 * nip + 1][1] = t4[3];
        }
#pragma unroll
        for (int ni = 0; ni < 4; ++ni)
#pragma unroll
            for (int mi = 0; mi < 2; ++mi) {
                mma16816(d[mi][ni], ah[mi], bh[ni][0], bh[ni][1]);
                mma16816(d[mi][ni], ah[mi], bl[ni][0], bl[ni][1]);
                mma16816(d[mi][ni], al[mi], bh[ni][0], bh[ni][1]);
            }
    }

#pragma unroll
    for (int mi = 0; mi < 2; ++mi) {
        const int row = m0 + wm * 32 + mi * 16 + lr;
#pragma unroll
        for (int ni = 0; ni < 4; ++ni) {
            const int col = wn * 32 + ni * 8 + lc;
            const float b0 = __ldg(&bias[col]), b1 = __ldg(&bias[col + 1]);
            *(float2*)(C + (size_t)row * 128 + col) =
                make_float2(d[mi][ni][0] + b0, d[mi][ni][1] + b1);
            *(float2*)(C + (size_t)(row + 8) * 128 + col) =
                make_float2(d[mi][ni][2] + b0, d[mi][ni][3] + b1);
        }
    }
}

// ---------------------------------------------------------------------------
extern "C" void kernel_launch(void* const* d_in, const int* in_sizes, int n_in,
                              void* d_out, int out_size)
{
    const float* emb      = (const float*)d_in[0];
    const float* w_self0  = (const float*)d_in[1];
    const float* b_self0  = (const float*)d_in[2];
    const float* w_neigh0 = (const float*)d_in[3];
    const float* b_neigh0 = (const float*)d_in[4];
    const float* w_self1  = (const float*)d_in[5];
    const float* b_self1  = (const float*)d_in[6];
    const float* w_neigh1 = (const float*)d_in[7];
    const float* b_neigh1 = (const float*)d_in[8];
    const float* fc_w     = (const float*)d_in[9];
    const float* fc_b     = (const float*)d_in[10];
    const int*   nodeids  = (const int*)d_in[11];
    const int*   neigh1   = (const int*)d_in[12];
    const int*   neigh2   = (const int*)d_in[13];
    float*       out      = (float*)d_out;

    __nv_bfloat16 *WHI, *WLO;
    float *F0, *F1, *Gg;
    cudaGetSymbolAddress((void**)&WHI, g_whi);
    cudaGetSymbolAddress((void**)&WLO, g_wlo);
    cudaGetSymbolAddress((void**)&F0, g_F0);
    cudaGetSymbolAddress((void**)&F1, g_F1);
    cudaGetSymbolAddress((void**)&Gg, g_G);

    cudaFuncSetAttribute(layer0_k, cudaFuncAttributeMaxDynamicSharedMemorySize, G_SMEM);
    cudaFuncSetAttribute(layer1_k, cudaFuncAttributeMaxDynamicSharedMemorySize, G_SMEM);
    cudaFuncSetAttribute(fc_k,     cudaFuncAttributeMaxDynamicSharedMemorySize, F_SMEM);

    conv_w<<<640, 256>>>(w_self0, w_neigh0, w_self1, w_neigh1, fc_w, WHI, WLO);

    layer0_k<<<2048, 256, G_SMEM>>>(emb, nodeids, neigh1, neigh2,
                                    WHI, WLO, b_self0, b_neigh0, F0, F1);
    layer1_k<<<512, 256, G_SMEM>>>(F0, F1, WHI, WLO, b_self1, b_neigh1, Gg);
    fc_k<<<B_ROOT / 64, 256, F_SMEM>>>(Gg, WHI + 131072, WLO + 131072, fc_b, out);
}

// round 9
// speedup vs baseline: 1.1903x; 1.0441x over previous
#include <cuda_runtime.h>
#include <cuda_bf16.h>
#include <cstdint>

// ---------------------------------------------------------------------------
// GraphSAGE, mma.sync bf16 hi/lo (3-product fp32-accurate).
// layer0_k: 4 segments in one launch; gemm_body = CTA 256 thr, M64 x N128,
//   K=256 in 4 chunks, A gather->regs->split->SMEM, W cp.async dbl-buffered,
//   108 KB SMEM -> 2 CTAs/SM.
// l1fc_k: 512 thr, M64 x N256 layer-1 tile + row L2-norm + FC, all fused.
// ---------------------------------------------------------------------------

#define B_ROOT 16384
#define R1     49152
#define RSA    72            // chunk tile row stride (bf16 elems)
#define RSH    264           // l1fc h / fc row stride

// gemm smem (bytes)
#define GA(b)  ((b) * 18432)                 // A: hi +0, lo +9216
#define GW(b)  (36864 + (b) * 36864)         // W: hi +0, lo +18432
#define G_SMEM 110592
// l1fc smem (bytes)
#define L_ASELF(b) ((b) * 36864)             // self A: hi +0, lo +9216
#define L_ANEI(b)  ((b) * 36864 + 18432)     // neigh A: hi +0, lo +9216
#define L_W(b)     (73728 + (b) * 73728)     // W(256 rows): hi +0, lo +36864
#define L_SMEM     221184
// stage-2 aliases (reused after stage-1 drains)
#define L_HH  0
#define L_HL  33792
#define L_SS  67584
#define L_FCH 73728
#define L_FCL 141312

// ---------------- scratch ----------------------------------------------------
__device__ float g_F0[B_ROOT * 256];
__device__ float g_F1[R1 * 256];
__device__ __nv_bfloat16 g_whi[5 * 32768];
__device__ __nv_bfloat16 g_wlo[5 * 32768];

// ---------------- helpers ----------------------------------------------------
__device__ __forceinline__ uint32_t smem_u32(const void* p) {
    uint32_t a;
    asm("{ .reg .u64 t; cvta.to.shared.u64 t, %1; cvt.u32.u64 %0, t; }"
        : "=r"(a) : "l"(p));
    return a;
}
__device__ __forceinline__ void split2(float a, float b, uint32_t& h, uint32_t& l) {
    __nv_bfloat16 ah = __float2bfloat16_rn(a), bh = __float2bfloat16_rn(b);
    __nv_bfloat16 al = __float2bfloat16_rn(a - __bfloat162float(ah));
    __nv_bfloat16 bl = __float2bfloat16_rn(b - __bfloat162float(bh));
    __nv_bfloat162 ph = __halves2bfloat162(ah, bh);
    __nv_bfloat162 pl = __halves2bfloat162(al, bl);
    h = *reinterpret_cast<uint32_t*>(&ph);
    l = *reinterpret_cast<uint32_t*>(&pl);
}
__device__ __forceinline__ void split8(const float* v, uint4& h4, uint4& l4) {
    uint32_t h[4], l[4];
#pragma unroll
    for (int i = 0; i < 4; ++i) split2(v[2 * i], v[2 * i + 1], h[i], l[i]);
    h4 = make_uint4(h[0], h[1], h[2], h[3]);
    l4 = make_uint4(l[0], l[1], l[2], l[3]);
}
__device__ __forceinline__ void mma16816(float* d, const uint32_t* a,
                                         uint32_t b0, uint32_t b1) {
    asm volatile(
        "mma.sync.aligned.m16n8k16.row.col.f32.bf16.bf16.f32 "
        "{%0,%1,%2,%3}, {%4,%5,%6,%7}, {%8,%9}, {%0,%1,%2,%3};"
        : "+f"(d[0]), "+f"(d[1]), "+f"(d[2]), "+f"(d[3])
        : "r"(a[0]), "r"(a[1]), "r"(a[2]), "r"(a[3]), "r"(b0), "r"(b1));
}
__device__ __forceinline__ void ldmx4(uint32_t* r, uint32_t a) {
    asm volatile("ldmatrix.sync.aligned.m8n8.x4.shared.b16 {%0,%1,%2,%3}, [%4];"
                 : "=r"(r[0]), "=r"(r[1]), "=r"(r[2]), "=r"(r[3]) : "r"(a));
}
__device__ __forceinline__ void cp16(uint32_t dst, const void* src) {
    asm volatile("cp.async.cg.shared.global [%0], [%1], 16;" :: "r"(dst), "l"(src));
}
#define CP_COMMIT() asm volatile("cp.async.commit_group;" ::: "memory")
#define CP_WAIT0()  asm volatile("cp.async.wait_group 0;"  ::: "memory")

// ---------------- weight pre-split --------------------------------------------
__global__ void conv_w(const float* __restrict__ a, const float* __restrict__ b,
                       const float* __restrict__ c, const float* __restrict__ d,
                       const float* __restrict__ e,
                       __nv_bfloat16* __restrict__ hi, __nv_bfloat16* __restrict__ lo) {
    int t = blockIdx.x * blockDim.x + threadIdx.x;
    const float* src[5] = {a, b, c, d, e};
    float x = src[t >> 15][t & 32767];
    __nv_bfloat16 h = __float2bfloat16_rn(x);
    hi[t] = h;
    lo[t] = __float2bfloat16_rn(x - __bfloat162float(h));
}

// ---------------- layer-0 GEMM body --------------------------------------------
// GATHER: 0 = A[idx[m]], 1 = mean_{j<KF} A[idx[m*KF+j]]
template <int GATHER, int KF>
__device__ __forceinline__ void
gemm_body(char* smem, const float* __restrict__ A, const int* __restrict__ idx,
          const __nv_bfloat16* __restrict__ w_hi, const __nv_bfloat16* __restrict__ w_lo,
          const float* __restrict__ bias,
          float* __restrict__ C, int ldc, int col_off, int m0)
{
    const uint32_t sb = smem_u32(smem);
    const int tid = threadIdx.x, lane = tid & 31, wid = tid >> 5;
    const int wm = wid >> 2, wn = wid & 3;
    const int lr = lane >> 2, lc = (lane & 3) * 2;
    const int g  = lane >> 3, lm = lane & 7;
    const int aro = ((g & 1) << 3) + lm, aco = (g >> 1) << 3;
    const int bro = ((g >> 1) << 3) + lm, bco = (g & 1) << 3;
    const int r  = tid >> 2, cq = (tid & 3) * 16;

    auto ISSUE_W = [&](int ch, int buf) {
        const int kb = ch * 64;
#pragma unroll
        for (int i = 0; i < 8; ++i) {
            int o = tid + i * 256;
            int plane = o >> 10, ix = o & 1023;
            int row = ix >> 3, c8 = (ix & 7) * 8;
            const __nv_bfloat16* src =
                (plane ? w_lo : w_hi) + (size_t)row * 256 + kb + c8;
            cp16(sb + GW(buf) + (plane ? 18432 : 0)
                 + (uint32_t)(row * RSA + c8) * 2, src);
        }
    };

    int rows[KF];
    if (GATHER == 0)      rows[0] = idx[m0 + r];
    else {
#pragma unroll
        for (int j = 0; j < KF; ++j) rows[j] = idx[(size_t)(m0 + r) * KF + j];
    }

    float v[16];
    auto PREF = [&](int ch) {
        const int kb = ch * 64;
#pragma unroll
        for (int i = 0; i < 16; ++i) v[i] = 0.f;
#pragma unroll
        for (int j = 0; j < KF; ++j) {
            const float4* p = (const float4*)(A + (size_t)rows[j] * 256 + kb + cq);
#pragma unroll
            for (int q = 0; q < 4; ++q) {
                float4 f = __ldg(p + q);
                v[q * 4 + 0] += f.x; v[q * 4 + 1] += f.y;
                v[q * 4 + 2] += f.z; v[q * 4 + 3] += f.w;
            }
        }
    };
    auto STORE = [&](int buf) {
        const float s = 1.0f / (float)KF;
        float w[16];
#pragma unroll
        for (int i = 0; i < 16; ++i) w[i] = v[i] * s;
        uint4 h0, l0, h1, l1;
        split8(w, h0, l0);
        split8(w + 8, h1, l1);
        char* base = smem + GA(buf) + (size_t)(r * RSA + cq) * 2;
        *(uint4*)(base)              = h0;
        *(uint4*)(base + 16)         = h1;
        *(uint4*)(base + 9216)       = l0;
        *(uint4*)(base + 9216 + 16)  = l1;
    };

    float d[2][4][4];
#pragma unroll
    for (int i = 0; i < 2; ++i)
#pragma unroll
        for (int j = 0; j < 4; ++j)
#pragma unroll
            for (int k = 0; k < 4; ++k) d[i][j][k] = 0.f;

    ISSUE_W(0, 0);
    CP_COMMIT();
    PREF(0);
    STORE(0);
    CP_WAIT0();
    __syncthreads();

#pragma unroll
    for (int ch = 0; ch < 4; ++ch) {
        const int cb = ch & 1, nb = cb ^ 1;
        if (ch < 3) {
            ISSUE_W(ch + 1, nb);
            CP_COMMIT();
            PREF(ch + 1);
        }
        const uint32_t aH = sb + GA(cb), aL = aH + 9216;
        const uint32_t wH = sb + GW(cb), wL = wH + 18432;
#pragma unroll
        for (int ks = 0; ks < 4; ++ks) {
            uint32_t ah[2][4], al[2][4];
#pragma unroll
            for (int mi = 0; mi < 2; ++mi) {
                uint32_t ad = (uint32_t)((wm * 32 + mi * 16 + aro) * RSA
                                         + ks * 16 + aco) * 2;
                ldmx4(ah[mi], aH + ad);
                ldmx4(al[mi], aL + ad);
            }
            uint32_t bh[4][2], bl[4][2];
#pragma unroll
            for (int nip = 0; nip < 2; ++nip) {
                uint32_t bd = (uint32_t)((wn * 32 + nip * 16 + bro) * RSA
                                         + ks * 16 + bco) * 2;
                uint32_t t4[4];
                ldmx4(t4, wH + bd);
                bh[2 * nip][0] = t4[0]; bh[2 * nip][1] = t4[1];
                bh[2 * nip + 1][0] = t4[2]; bh[2 * nip + 1][1] = t4[3];
                ldmx4(t4, wL + bd);
                bl[2 * nip][0] = t4[0]; bl[2 * nip][1] = t4[1];
                bl[2 * nip + 1][0] = t4[2]; bl[2 * nip + 1][1] = t4[3];
            }
#pragma unroll
            for (int ni = 0; ni < 4; ++ni)
#pragma unroll
                for (int mi = 0; mi < 2; ++mi) {
                    mma16816(d[mi][ni], ah[mi], bh[ni][0], bh[ni][1]);
                    mma16816(d[mi][ni], ah[mi], bl[ni][0], bl[ni][1]);
                    mma16816(d[mi][ni], al[mi], bh[ni][0], bh[ni][1]);
                }
        }
        if (ch < 3) {
            STORE(nb);
            CP_WAIT0();
        }
        __syncthreads();
    }

#pragma unroll
    for (int mi = 0; mi < 2; ++mi) {
        const int row = m0 + wm * 32 + mi * 16 + lr;
#pragma unroll
        for (int ni = 0; ni < 4; ++ni) {
            const int col = wn * 32 + ni * 8 + lc;
            const float b0 = __ldg(&bias[col]), b1 = __ldg(&bias[col + 1]);
            *(float2*)(C + (size_t)row * ldc + col_off + col) =
                make_float2(fmaxf(d[mi][ni][0] + b0, 0.f),
                            fmaxf(d[mi][ni][1] + b1, 0.f));
            *(float2*)(C + (size_t)(row + 8) * ldc + col_off + col) =
                make_float2(fmaxf(d[mi][ni][2] + b0, 0.f),
                            fmaxf(d[mi][ni][3] + b1, 0.f));
        }
    }
}

// ---------------- layer 0: 4 segments, one launch -------------------------------
__global__ void __launch_bounds__(256, 2)
layer0_k(const float* __restrict__ emb,
         const int* __restrict__ nodeids, const int* __restrict__ neigh1,
         const int* __restrict__ neigh2,
         const __nv_bfloat16* __restrict__ whi, const __nv_bfloat16* __restrict__ wlo,
         const float* __restrict__ bs0, const float* __restrict__ bn0,
         float* __restrict__ F0, float* __restrict__ F1)
{
    extern __shared__ char smem[];
    const int bid = blockIdx.x;
    if (bid < 256) {
        gemm_body<0, 1>(smem, emb, nodeids, whi, wlo, bs0, F0, 256, 0, bid * 64);
    } else if (bid < 512) {
        gemm_body<1, 3>(smem, emb, neigh1, whi + 32768, wlo + 32768, bn0,
                        F0, 256, 128, (bid - 256) * 64);
    } else if (bid < 1280) {
        gemm_body<0, 1>(smem, emb, neigh1, whi, wlo, bs0,
                        F1, 256, 0, (bid - 512) * 64);
    } else {
        gemm_body<1, 5>(smem, emb, neigh2, whi + 32768, wlo + 32768, bn0,
                        F1, 256, 128, (bid - 1280) * 64);
    }
}

// ---------------- fused layer1 + L2-norm + FC -----------------------------------
// 512 thr, M=64, stage1 N=256 (self|neigh), stage2 FC N=128.
__global__ void __launch_bounds__(512, 1)
l1fc_k(const float* __restrict__ F0, const float* __restrict__ F1,
       const __nv_bfloat16* __restrict__ w1_hi, const __nv_bfloat16* __restrict__ w1_lo,
       const float* __restrict__ bS, const float* __restrict__ bN,
       const __nv_bfloat16* __restrict__ fc_hi, const __nv_bfloat16* __restrict__ fc_lo,
       const float* __restrict__ fcb, float* __restrict__ out)
{
    extern __shared__ char smem[];
    const uint32_t sb = smem_u32(smem);
    const int tid = threadIdx.x, lane = tid & 31, wid = tid >> 5;
    const int wm = wid >> 3, wn = wid & 7;          // stage1: 2m x 8n, warp 32x32
    const int lr = lane >> 2, lc = (lane & 3) * 2;
    const int g  = lane >> 3, lm = lane & 7;
    const int aro = ((g & 1) << 3) + lm, aco = (g >> 1) << 3;
    const int bro = ((g >> 1) << 3) + lm, bco = (g & 1) << 3;
    const int m0 = blockIdx.x * 64;

    const bool isSelf = tid < 256;
    const int lt = tid & 255;
    const int r = lt >> 2, cq = (lt & 3) * 16;

    // stage1 W: stacked 256 rows (Ws1 | Wn1), per-chunk 4096 cp16 / 512 thr
    auto ISSUE_W = [&](int ch, int buf) {
        const int kb = ch * 64;
#pragma unroll
        for (int i = 0; i < 8; ++i) {
            int o = tid + i * 512;
            int plane = o >> 11, ix = o & 2047;
            int row = ix >> 3, c8 = (ix & 7) * 8;
            const __nv_bfloat16* src =
                (plane ? w1_lo : w1_hi) + (size_t)row * 256 + kb + c8;
            cp16(sb + L_W(buf) + (plane ? 36864 : 0)
                 + (uint32_t)(row * RSA + c8) * 2, src);
        }
    };

    float v[16];
    auto PREF = [&](int ch) {
        const int kb = ch * 64;
        if (isSelf) {
            const float4* p = (const float4*)(F0 + (size_t)(m0 + r) * 256 + kb + cq);
#pragma unroll
            for (int q = 0; q < 4; ++q) {
                float4 f = __ldg(p + q);
                v[q * 4 + 0] = f.x; v[q * 4 + 1] = f.y;
                v[q * 4 + 2] = f.z; v[q * 4 + 3] = f.w;
            }
        } else {
#pragma unroll
            for (int i = 0; i < 16; ++i) v[i] = 0.f;
#pragma unroll
            for (int j = 0; j < 3; ++j) {
                const float4* p = (const float4*)(F1
                    + (size_t)((m0 + r) * 3 + j) * 256 + kb + cq);
#pragma unroll
                for (int q = 0; q < 4; ++q) {
                    float4 f = __ldg(p + q);
                    v[q * 4 + 0] += f.x; v[q * 4 + 1] += f.y;
                    v[q * 4 + 2] += f.z; v[q * 4 + 3] += f.w;
                }
            }
#pragma unroll
            for (int i = 0; i < 16; ++i) v[i] *= (1.0f / 3.0f);
        }
    };
    auto STORE = [&](int buf) {
        uint4 h0, l0, h1, l1;
        split8(v, h0, l0);
        split8(v + 8, h1, l1);
        char* base = smem + (isSelf ? L_ASELF(buf) : L_ANEI(buf))
                   + (size_t)(r * RSA + cq) * 2;
        *(uint4*)(base)             = h0;
        *(uint4*)(base + 16)        = h1;
        *(uint4*)(base + 9216)      = l0;
        *(uint4*)(base + 9216 + 16) = l1;
    };

    float d[2][4][4];
#pragma unroll
    for (int i = 0; i < 2; ++i)
#pragma unroll
        for (int j = 0; j < 4; ++j)
#pragma unroll
            for (int k = 0; k < 4; ++k) d[i][j][k] = 0.f;

    ISSUE_W(0, 0);
    CP_COMMIT();
    PREF(0);
    STORE(0);
    CP_WAIT0();
    __syncthreads();

#pragma unroll
    for (int ch = 0; ch < 4; ++ch) {
        const int cb = ch & 1, nb = cb ^ 1;
        if (ch < 3) {
            ISSUE_W(ch + 1, nb);
            CP_COMMIT();
            PREF(ch + 1);
        }
        const uint32_t aB = sb + (wn < 4 ? L_ASELF(cb) : L_ANEI(cb));
        const uint32_t aH = aB, aL = aB + 9216;
        const uint32_t wH = sb + L_W(cb), wL = wH + 36864;
#pragma unroll
        for (int ks = 0; ks < 4; ++ks) {
            uint32_t ah[2][4], al[2][4];
#pragma unroll
            for (int mi = 0; mi < 2; ++mi) {
                uint32_t ad = (uint32_t)((wm * 32 + mi * 16 + aro) * RSA
                                         + ks * 16 + aco) * 2;
                ldmx4(ah[mi], aH + ad);
                ldmx4(al[mi], aL + ad);
            }
            uint32_t bh[4][2], bl[4][2];
#pragma unroll
            for (int nip = 0; nip < 2; ++nip) {
                uint32_t bd = (uint32_t)((wn * 32 + nip * 16 + bro) * RSA
                                         + ks * 16 + bco) * 2;
                uint32_t t4[4];
                ldmx4(t4, wH + bd);
                bh[2 * nip][0] = t4[0]; bh[2 * nip][1] = t4[1];
                bh[2 * nip + 1][0] = t4[2]; bh[2 * nip + 1][1] = t4[3];
                ldmx4(t4, wL + bd);
                bl[2 * nip][0] = t4[0]; bl[2 * nip][1] = t4[1];
                bl[2 * nip + 1][0] = t4[2]; bl[2 * nip + 1][1] = t4[3];
            }
#pragma unroll
            for (int ni = 0; ni < 4; ++ni)
#pragma unroll
                for (int mi = 0; mi < 2; ++mi) {
                    mma16816(d[mi][ni], ah[mi], bh[ni][0], bh[ni][1]);
                    mma16816(d[mi][ni], ah[mi], bl[ni][0], bl[ni][1]);
                    mma16816(d[mi][ni], al[mi], bh[ni][0], bh[ni][1]);
                }
        }
        if (ch < 3) {
            STORE(nb);
            CP_WAIT0();
        }
        __syncthreads();
    }

    // ---- issue fc W loads (8192 cp16 / 512 thr), hidden under epilogue ------
#pragma unroll
    for (int i = 0; i < 16; ++i) {
        int o = tid + i * 512;
        int plane = o >> 12, ix = o & 4095;
        int row = ix >> 5, c8 = (ix & 31) * 8;
        const __nv_bfloat16* src = (plane ? fc_lo : fc_hi) + (size_t)row * 256 + c8;
        cp16(sb + L_FCH + (plane ? 67584 : 0) + (uint32_t)(row * RSH + c8) * 2, src);
    }
    CP_COMMIT();

    // ---- epilogue: bias + relu + row sum-of-squares --------------------------
    float* ss = (float*)(smem + L_SS);
    if (tid < 64) ss[tid] = 0.f;
    __syncthreads();

#pragma unroll
    for (int mi = 0; mi < 2; ++mi) {
        const int r0 = wm * 32 + mi * 16 + lr;
        float s0 = 0.f, s1 = 0.f;
#pragma unroll
        for (int ni = 0; ni < 4; ++ni) {
            const int col = wn * 32 + ni * 8 + lc;
            const float b0 = (col < 128) ? bS[col] : bN[col - 128];
            const float b1 = (col + 1 < 128) ? bS[col + 1] : bN[col - 127];
            d[mi][ni][0] = fmaxf(d[mi][ni][0] + b0, 0.f);
            d[mi][ni][1] = fmaxf(d[mi][ni][1] + b1, 0.f);
            d[mi][ni][2] = fmaxf(d[mi][ni][2] + b0, 0.f);
            d[mi][ni][3] = fmaxf(d[mi][ni][3] + b1, 0.f);
            s0 += d[mi][ni][0] * d[mi][ni][0] + d[mi][ni][1] * d[mi][ni][1];
            s1 += d[mi][ni][2] * d[mi][ni][2] + d[mi][ni][3] * d[mi][ni][3];
        }
        s0 += __shfl_xor_sync(0xffffffffu, s0, 1);
        s0 += __shfl_xor_sync(0xffffffffu, s0, 2);
        s1 += __shfl_xor_sync(0xffffffffu, s1, 1);
        s1 += __shfl_xor_sync(0xffffffffu, s1, 2);
        if ((lane & 3) == 0) {
            atomicAdd(&ss[r0], s0);
            atomicAdd(&ss[r0 + 8], s1);
        }
    }
    __syncthreads();

    // scale + split -> h tiles (reuse stage-1 A region)
#pragma unroll
    for (int mi = 0; mi < 2; ++mi) {
        const int r0 = wm * 32 + mi * 16 + lr;
        const float sc0 = 1.0f / fmaxf(sqrtf(ss[r0]), 1e-12f);
        const float sc1 = 1.0f / fmaxf(sqrtf(ss[r0 + 8]), 1e-12f);
#pragma unroll
        for (int ni = 0; ni < 4; ++ni) {
            const int col = wn * 32 + ni * 8 + lc;
            uint32_t h, l;
            split2(d[mi][ni][0] * sc0, d[mi][ni][1] * sc0, h, l);
            *(uint32_t*)(smem + L_HH + (size_t)(r0 * RSH + col) * 2) = h;
            *(uint32_t*)(smem + L_HL + (size_t)(r0 * RSH + col) * 2) = l;
            split2(d[mi][ni][2] * sc1, d[mi][ni][3] * sc1, h, l);
            *(uint32_t*)(smem + L_HH + (size_t)((r0 + 8) * RSH + col) * 2) = h;
            *(uint32_t*)(smem + L_HL + (size_t)((r0 + 8) * RSH + col) * 2) = l;
        }
    }
    CP_WAIT0();
    __syncthreads();

    // ---- stage 2: out = h @ fc^T  (M=64, N=128, K=256), warp 32x16 ----------
    const int wm2 = wid & 1, wn2 = wid >> 1;        // 2m x 8n
    float e[2][2][4];
#pragma unroll
    for (int i = 0; i < 2; ++i)
#pragma unroll
        for (int j = 0; j < 2; ++j)
#pragma unroll
            for (int k = 0; k < 4; ++k) e[i][j][k] = 0.f;

#pragma unroll
    for (int ks = 0; ks < 16; ++ks) {
        uint32_t ah[2][4], al[2][4];
#pragma unroll
        for (int mi = 0; mi < 2; ++mi) {
            uint32_t ad = (uint32_t)((wm2 * 32 + mi * 16 + aro) * RSH
                                     + ks * 16 + aco) * 2;
            ldmx4(ah[mi], sb + L_HH + ad);
            ldmx4(al[mi], sb + L_HL + ad);
        }
        uint32_t bd = (uint32_t)((wn2 * 16 + bro) * RSH + ks * 16 + bco) * 2;
        uint32_t th[4], tl[4];
        ldmx4(th, sb + L_FCH + bd);
        ldmx4(tl, sb + L_FCL + bd);
#pragma unroll
        for (int ni = 0; ni < 2; ++ni) {
            const uint32_t bh0 = th[2 * ni], bh1 = th[2 * ni + 1];
            const uint32_t bl0 = tl[2 * ni], bl1 = tl[2 * ni + 1];
#pragma unroll
            for (int mi = 0; mi < 2; ++mi) {
                mma16816(e[mi][ni], ah[mi], bh0, bh1);
                mma16816(e[mi][ni], ah[mi], bl0, bl1);
                mma16816(e[mi][ni], al[mi], bh0, bh1);
            }
        }
    }

#pragma unroll
    for (int mi = 0; mi < 2; ++mi) {
        const int row = m0 + wm2 * 32 + mi * 16 + lr;
#pragma unroll
        for (int ni = 0; ni < 2; ++ni) {
            const int col = wn2 * 16 + ni * 8 + lc;
            const float b0 = __ldg(&fcb[col]), b1 = __ldg(&fcb[col + 1]);
            *(float2*)(out + (size_t)row * 128 + col) =
                make_float2(e[mi][ni][0] + b0, e[mi][ni][1] + b1);
            *(float2*)(out + (size_t)(row + 8) * 128 + col) =
                make_float2(e[mi][ni][2] + b0, e[mi][ni][3] + b1);
        }
    }
}

// ---------------------------------------------------------------------------
extern "C" void kernel_launch(void* const* d_in, const int* in_sizes, int n_in,
                              void* d_out, int out_size)
{
    const float* emb      = (const float*)d_in[0];
    const float* w_self0  = (const float*)d_in[1];
    const float* b_self0  = (const float*)d_in[2];
    const float* w_neigh0 = (const float*)d_in[3];
    const float* b_neigh0 = (const float*)d_in[4];
    const float* w_self1  = (const float*)d_in[5];
    const float* b_self1  = (const float*)d_in[6];
    const float* w_neigh1 = (const float*)d_in[7];
    const float* b_neigh1 = (const float*)d_in[8];
    const float* fc_w     = (const float*)d_in[9];
    const float* fc_b     = (const float*)d_in[10];
    const int*   nodeids  = (const int*)d_in[11];
    const int*   neigh1   = (const int*)d_in[12];
    const int*   neigh2   = (const int*)d_in[13];
    float*       out      = (float*)d_out;

    __nv_bfloat16 *WHI, *WLO;
    float *F0, *F1;
    cudaGetSymbolAddress((void**)&WHI, g_whi);
    cudaGetSymbolAddress((void**)&WLO, g_wlo);
    cudaGetSymbolAddress((void**)&F0, g_F0);
    cudaGetSymbolAddress((void**)&F1, g_F1);

    cudaFuncSetAttribute(layer0_k, cudaFuncAttributeMaxDynamicSharedMemorySize, G_SMEM);
    cudaFuncSetAttribute(l1fc_k,   cudaFuncAttributeMaxDynamicSharedMemorySize, L_SMEM);

    conv_w<<<640, 256>>>(w_self0, w_neigh0, w_self1, w_neigh1, fc_w, WHI, WLO);

    layer0_k<<<2048, 256, G_SMEM>>>(emb, nodeids, neigh1, neigh2,
                                    WHI, WLO, b_self0, b_neigh0, F0, F1);

    // fused layer1 + normalize + FC (stacked Ws1|Wn1 at WHI+65536)
    l1fc_k<<<B_ROOT / 64, 512, L_SMEM>>>(F0, F1,
                                         WHI + 65536, WLO + 65536,
                                         b_self1, b_neigh1,
                                         WHI + 131072, WLO + 131072,
                                         fc_b, out);
}

// round 10
// speedup vs baseline: 1.2311x; 1.0342x over previous
#include <cuda_runtime.h>
#include <cuda_bf16.h>
#include <cstdint>

// ---------------------------------------------------------------------------
// GraphSAGE, mma.sync bf16 hi/lo (3-product fp32-accurate).
// layer0_k: 4 segments in one launch; gemm_body = CTA 256 thr, M64 x N128,
//   K=256 in 4 chunks, A gather->regs(batched)->split->SMEM, W cp.async
//   dbl-buffered, 108 KB SMEM -> 2 CTAs/SM.
// l1fc_k: 512 thr, M64 x N256 layer-1 tile + row L2-norm + FC, all fused.
// ---------------------------------------------------------------------------

#define B_ROOT 16384
#define R1     49152
#define RSA    72            // chunk tile row stride (bf16 elems)
#define RSH    264           // l1fc h / fc row stride

// gemm smem (bytes)
#define GA(b)  ((b) * 18432)                 // A: hi +0, lo +9216
#define GW(b)  (36864 + (b) * 36864)         // W: hi +0, lo +18432
#define G_SMEM 110592
// l1fc smem (bytes)
#define L_ASELF(b) ((b) * 36864)             // self A: hi +0, lo +9216
#define L_ANEI(b)  ((b) * 36864 + 18432)     // neigh A: hi +0, lo +9216
#define L_W(b)     (73728 + (b) * 73728)     // W(256 rows): hi +0, lo +36864
#define L_SMEM     221184
// stage-2 aliases (reused after stage-1 drains)
#define L_HH  0
#define L_HL  33792
#define L_SS  67584
#define L_FCH 73728
#define L_FCL 141312

// ---------------- scratch ----------------------------------------------------
__device__ float g_F0[B_ROOT * 256];
__device__ float g_F1[R1 * 256];
__device__ __nv_bfloat16 g_whi[5 * 32768];
__device__ __nv_bfloat16 g_wlo[5 * 32768];

// ---------------- helpers ----------------------------------------------------
__device__ __forceinline__ uint32_t smem_u32(const void* p) {
    uint32_t a;
    asm("{ .reg .u64 t; cvta.to.shared.u64 t, %1; cvt.u32.u64 %0, t; }"
        : "=r"(a) : "l"(p));
    return a;
}
__device__ __forceinline__ void split2(float a, float b, uint32_t& h, uint32_t& l) {
    __nv_bfloat16 ah = __float2bfloat16_rn(a), bh = __float2bfloat16_rn(b);
    __nv_bfloat16 al = __float2bfloat16_rn(a - __bfloat162float(ah));
    __nv_bfloat16 bl = __float2bfloat16_rn(b - __bfloat162float(bh));
    __nv_bfloat162 ph = __halves2bfloat162(ah, bh);
    __nv_bfloat162 pl = __halves2bfloat162(al, bl);
    h = *reinterpret_cast<uint32_t*>(&ph);
    l = *reinterpret_cast<uint32_t*>(&pl);
}
__device__ __forceinline__ void split8(const float* v, uint4& h4, uint4& l4) {
    uint32_t h[4], l[4];
#pragma unroll
    for (int i = 0; i < 4; ++i) split2(v[2 * i], v[2 * i + 1], h[i], l[i]);
    h4 = make_uint4(h[0], h[1], h[2], h[3]);
    l4 = make_uint4(l[0], l[1], l[2], l[3]);
}
__device__ __forceinline__ void mma16816(float* d, const uint32_t* a,
                                         uint32_t b0, uint32_t b1) {
    asm volatile(
        "mma.sync.aligned.m16n8k16.row.col.f32.bf16.bf16.f32 "
        "{%0,%1,%2,%3}, {%4,%5,%6,%7}, {%8,%9}, {%0,%1,%2,%3};"
        : "+f"(d[0]), "+f"(d[1]), "+f"(d[2]), "+f"(d[3])
        : "r"(a[0]), "r"(a[1]), "r"(a[2]), "r"(a[3]), "r"(b0), "r"(b1));
}
__device__ __forceinline__ void ldmx4(uint32_t* r, uint32_t a) {
    asm volatile("ldmatrix.sync.aligned.m8n8.x4.shared.b16 {%0,%1,%2,%3}, [%4];"
                 : "=r"(r[0]), "=r"(r[1]), "=r"(r[2]), "=r"(r[3]) : "r"(a));
}
__device__ __forceinline__ void cp16(uint32_t dst, const void* src) {
    asm volatile("cp.async.cg.shared.global [%0], [%1], 16;" :: "r"(dst), "l"(src));
}
#define CP_COMMIT() asm volatile("cp.async.commit_group;" ::: "memory")
#define CP_WAIT0()  asm volatile("cp.async.wait_group 0;"  ::: "memory")

// ---------------- weight pre-split (vectorized) --------------------------------
__global__ void conv_w(const float* __restrict__ a, const float* __restrict__ b,
                       const float* __restrict__ c, const float* __restrict__ d,
                       const float* __restrict__ e,
                       __nv_bfloat16* __restrict__ hi, __nv_bfloat16* __restrict__ lo) {
    int t = blockIdx.x * blockDim.x + threadIdx.x;   // 40960 threads
    int base = t * 4;                                 // 163840 elems total
    const float* src[5] = {a, b, c, d, e};
    float4 f = __ldg((const float4*)(src[base >> 15] + (base & 32767)));
    uint32_t h0, l0, h1, l1;
    split2(f.x, f.y, h0, l0);
    split2(f.z, f.w, h1, l1);
    *(uint2*)(hi + base) = make_uint2(h0, h1);
    *(uint2*)(lo + base) = make_uint2(l0, l1);
}

// ---------------- layer-0 GEMM body --------------------------------------------
// GATHER: 0 = A[idx[m]], 1 = mean_{j<KF} A[idx[m*KF+j]]
template <int GATHER, int KF>
__device__ __forceinline__ void
gemm_body(char* smem, const float* __restrict__ A, const int* __restrict__ idx,
          const __nv_bfloat16* __restrict__ w_hi, const __nv_bfloat16* __restrict__ w_lo,
          const float* __restrict__ bias,
          float* __restrict__ C, int ldc, int col_off, int m0)
{
    const uint32_t sb = smem_u32(smem);
    const int tid = threadIdx.x, lane = tid & 31, wid = tid >> 5;
    const int wm = wid >> 2, wn = wid & 3;
    const int lr = lane >> 2, lc = (lane & 3) * 2;
    const int g  = lane >> 3, lm = lane & 7;
    const int aro = ((g & 1) << 3) + lm, aco = (g >> 1) << 3;
    const int bro = ((g >> 1) << 3) + lm, bco = (g & 1) << 3;
    const int r  = tid >> 2, cq = (tid & 3) * 16;

    auto ISSUE_W = [&](int ch, int buf) {
        const int kb = ch * 64;
#pragma unroll
        for (int i = 0; i < 8; ++i) {
            int o = tid + i * 256;
            int plane = o >> 10, ix = o & 1023;
            int row = ix >> 3, c8 = (ix & 7) * 8;
            const __nv_bfloat16* src =
                (plane ? w_lo : w_hi) + (size_t)row * 256 + kb + c8;
            cp16(sb + GW(buf) + (plane ? 18432 : 0)
                 + (uint32_t)(row * RSA + c8) * 2, src);
        }
    };

    int rows[KF];
    if (GATHER == 0)      rows[0] = idx[m0 + r];
    else {
#pragma unroll
        for (int j = 0; j < KF; ++j) rows[j] = idx[(size_t)(m0 + r) * KF + j];
    }

    float v[16];
    auto PREF = [&](int ch) {
        const int kb = ch * 64;
        if (GATHER == 0) {
            const float4* p = (const float4*)(A + (size_t)rows[0] * 256 + kb + cq);
            float4 t0 = __ldg(p), t1 = __ldg(p + 1), t2 = __ldg(p + 2), t3 = __ldg(p + 3);
            v[0]  = t0.x; v[1]  = t0.y; v[2]  = t0.z; v[3]  = t0.w;
            v[4]  = t1.x; v[5]  = t1.y; v[6]  = t1.z; v[7]  = t1.w;
            v[8]  = t2.x; v[9]  = t2.y; v[10] = t2.z; v[11] = t2.w;
            v[12] = t3.x; v[13] = t3.y; v[14] = t3.z; v[15] = t3.w;
        } else {
#pragma unroll
            for (int i = 0; i < 16; ++i) v[i] = 0.f;
#pragma unroll
            for (int h = 0; h < 2; ++h) {          // two 8-float halves
                float4 t[2 * KF];                  // independent loads -> high MLP
#pragma unroll
                for (int j = 0; j < KF; ++j) {
                    const float4* p = (const float4*)(A + (size_t)rows[j] * 256
                                                      + kb + cq + h * 8);
                    t[j * 2]     = __ldg(p);
                    t[j * 2 + 1] = __ldg(p + 1);
                }
#pragma unroll
                for (int j = 0; j < KF; ++j)
#pragma unroll
                    for (int q = 0; q < 2; ++q) {
                        const float4 f = t[j * 2 + q];
                        const int o = h * 8 + q * 4;
                        v[o + 0] += f.x; v[o + 1] += f.y;
                        v[o + 2] += f.z; v[o + 3] += f.w;
                    }
            }
        }
    };
    auto STORE = [&](int buf) {
        const float s = 1.0f / (float)KF;
        float w[16];
#pragma unroll
        for (int i = 0; i < 16; ++i) w[i] = v[i] * s;
        uint4 h0, l0, h1, l1;
        split8(w, h0, l0);
        split8(w + 8, h1, l1);
        char* base = smem + GA(buf) + (size_t)(r * RSA + cq) * 2;
        *(uint4*)(base)              = h0;
        *(uint4*)(base + 16)         = h1;
        *(uint4*)(base + 9216)       = l0;
        *(uint4*)(base + 9216 + 16)  = l1;
    };

    float d[2][4][4];
#pragma unroll
    for (int i = 0; i < 2; ++i)
#pragma unroll
        for (int j = 0; j < 4; ++j)
#pragma unroll
            for (int k = 0; k < 4; ++k) d[i][j][k] = 0.f;

    ISSUE_W(0, 0);
    CP_COMMIT();
    PREF(0);
    STORE(0);
    CP_WAIT0();
    __syncthreads();

#pragma unroll
    for (int ch = 0; ch < 4; ++ch) {
        const int cb = ch & 1, nb = cb ^ 1;
        if (ch < 3) {
            ISSUE_W(ch + 1, nb);
            CP_COMMIT();
            PREF(ch + 1);
        }
        const uint32_t aH = sb + GA(cb), aL = aH + 9216;
        const uint32_t wH = sb + GW(cb), wL = wH + 18432;
#pragma unroll
        for (int ks = 0; ks < 4; ++ks) {
            uint32_t ah[2][4], al[2][4];
#pragma unroll
            for (int mi = 0; mi < 2; ++mi) {
                uint32_t ad = (uint32_t)((wm * 32 + mi * 16 + aro) * RSA
                                         + ks * 16 + aco) * 2;
                ldmx4(ah[mi], aH + ad);
                ldmx4(al[mi], aL + ad);
            }
            uint32_t bh[4][2], bl[4][2];
#pragma unroll
            for (int nip = 0; nip < 2; ++nip) {
                uint32_t bd = (uint32_t)((wn * 32 + nip * 16 + bro) * RSA
                                         + ks * 16 + bco) * 2;
                uint32_t t4[4];
                ldmx4(t4, wH + bd);
                bh[2 * nip][0] = t4[0]; bh[2 * nip][1] = t4[1];
                bh[2 * nip + 1][0] = t4[2]; bh[2 * nip + 1][1] = t4[3];
                ldmx4(t4, wL + bd);
                bl[2 * nip][0] = t4[0]; bl[2 * nip][1] = t4[1];
                bl[2 * nip + 1][0] = t4[2]; bl[2 * nip + 1][1] = t4[3];
            }
#pragma unroll
            for (int ni = 0; ni < 4; ++ni)
#pragma unroll
                for (int mi = 0; mi < 2; ++mi) {
                    mma16816(d[mi][ni], ah[mi], bh[ni][0], bh[ni][1]);
                    mma16816(d[mi][ni], ah[mi], bl[ni][0], bl[ni][1]);
                    mma16816(d[mi][ni], al[mi], bh[ni][0], bh[ni][1]);
                }
        }
        if (ch < 3) {
            STORE(nb);
            CP_WAIT0();
        }
        __syncthreads();
    }

#pragma unroll
    for (int mi = 0; mi < 2; ++mi) {
        const int row = m0 + wm * 32 + mi * 16 + lr;
#pragma unroll
        for (int ni = 0; ni < 4; ++ni) {
            const int col = wn * 32 + ni * 8 + lc;
            const float b0 = __ldg(&bias[col]), b1 = __ldg(&bias[col + 1]);
            *(float2*)(C + (size_t)row * ldc + col_off + col) =
                make_float2(fmaxf(d[mi][ni][0] + b0, 0.f),
                            fmaxf(d[mi][ni][1] + b1, 0.f));
            *(float2*)(C + (size_t)(row + 8) * ldc + col_off + col) =
                make_float2(fmaxf(d[mi][ni][2] + b0, 0.f),
                            fmaxf(d[mi][ni][3] + b1, 0.f));
        }
    }
}

// ---------------- layer 0: 4 segments, one launch -------------------------------
// order: mean5 (longest) first; the two neigh1-row readers adjacent.
// bid [0,768)    : F1 neigh = mean5 emb[neigh2]  @ Wn0
// bid [768,1536) : F1 self  = emb[neigh1]        @ Ws0
// bid [1536,1792): F0 neigh = mean3 emb[neigh1]  @ Wn0
// bid [1792,2048): F0 self  = emb[nodeids]       @ Ws0
__global__ void __launch_bounds__(256, 2)
layer0_k(const float* __restrict__ emb,
         const int* __restrict__ nodeids, const int* __restrict__ neigh1,
         const int* __restrict__ neigh2,
         const __nv_bfloat16* __restrict__ whi, const __nv_bfloat16* __restrict__ wlo,
         const float* __restrict__ bs0, const float* __restrict__ bn0,
         float* __restrict__ F0, float* __restrict__ F1)
{
    extern __shared__ char smem[];
    const int bid = blockIdx.x;
    if (bid < 768) {
        gemm_body<1, 5>(smem, emb, neigh2, whi + 32768, wlo + 32768, bn0,
                        F1, 256, 128, bid * 64);
    } else if (bid < 1536) {
        gemm_body<0, 1>(smem, emb, neigh1, whi, wlo, bs0,
                        F1, 256, 0, (bid - 768) * 64);
    } else if (bid < 1792) {
        gemm_body<1, 3>(smem, emb, neigh1, whi + 32768, wlo + 32768, bn0,
                        F0, 256, 128, (bid - 1536) * 64);
    } else {
        gemm_body<0, 1>(smem, emb, nodeids, whi, wlo, bs0,
                        F0, 256, 0, (bid - 1792) * 64);
    }
}

// ---------------- fused layer1 + L2-norm + FC -----------------------------------
__global__ void __launch_bounds__(512, 1)
l1fc_k(const float* __restrict__ F0, const float* __restrict__ F1,
       const __nv_bfloat16* __restrict__ w1_hi, const __nv_bfloat16* __restrict__ w1_lo,
       const float* __restrict__ bS, const float* __restrict__ bN,
       const __nv_bfloat16* __restrict__ fc_hi, const __nv_bfloat16* __restrict__ fc_lo,
       const float* __restrict__ fcb, float* __restrict__ out)
{
    extern __shared__ char smem[];
    const uint32_t sb = smem_u32(smem);
    const int tid = threadIdx.x, lane = tid & 31, wid = tid >> 5;
    const int wm = wid >> 3, wn = wid & 7;          // stage1: 2m x 8n, warp 32x32
    const int lr = lane >> 2, lc = (lane & 3) * 2;
    const int g  = lane >> 3, lm = lane & 7;
    const int aro = ((g & 1) << 3) + lm, aco = (g >> 1) << 3;
    const int bro = ((g >> 1) << 3) + lm, bco = (g & 1) << 3;
    const int m0 = blockIdx.x * 64;

    const bool isSelf = tid < 256;
    const int lt = tid & 255;
    const int r = lt >> 2, cq = (lt & 3) * 16;

    auto ISSUE_W = [&](int ch, int buf) {
        const int kb = ch * 64;
#pragma unroll
        for (int i = 0; i < 8; ++i) {
            int o = tid + i * 512;
            int plane = o >> 11, ix = o & 2047;
            int row = ix >> 3, c8 = (ix & 7) * 8;
            const __nv_bfloat16* src =
                (plane ? w1_lo : w1_hi) + (size_t)row * 256 + kb + c8;
            cp16(sb + L_W(buf) + (plane ? 36864 : 0)
                 + (uint32_t)(row * RSA + c8) * 2, src);
        }
    };

    float v[16];
    auto PREF = [&](int ch) {
        const int kb = ch * 64;
        if (isSelf) {
            const float4* p = (const float4*)(F0 + (size_t)(m0 + r) * 256 + kb + cq);
            float4 t0 = __ldg(p), t1 = __ldg(p + 1), t2 = __ldg(p + 2), t3 = __ldg(p + 3);
            v[0]  = t0.x; v[1]  = t0.y; v[2]  = t0.z; v[3]  = t0.w;
            v[4]  = t1.x; v[5]  = t1.y; v[6]  = t1.z; v[7]  = t1.w;
            v[8]  = t2.x; v[9]  = t2.y; v[10] = t2.z; v[11] = t2.w;
            v[12] = t3.x; v[13] = t3.y; v[14] = t3.z; v[15] = t3.w;
        } else {
#pragma unroll
            for (int i = 0; i < 16; ++i) v[i] = 0.f;
#pragma unroll
            for (int h = 0; h < 2; ++h) {
                float4 t[6];
#pragma unroll
                for (int j = 0; j < 3; ++j) {
                    const float4* p = (const float4*)(F1
                        + (size_t)((m0 + r) * 3 + j) * 256 + kb + cq + h * 8);
                    t[j * 2]     = __ldg(p);
                    t[j * 2 + 1] = __ldg(p + 1);
                }
#pragma unroll
                for (int j = 0; j < 3; ++j)
#pragma unroll
                    for (int q = 0; q < 2; ++q) {
                        const float4 f = t[j * 2 + q];
                        const int o = h * 8 + q * 4;
                        v[o + 0] += f.x; v[o + 1] += f.y;
                        v[o + 2] += f.z; v[o + 3] += f.w;
                    }
            }
#pragma unroll
            for (int i = 0; i < 16; ++i) v[i] *= (1.0f / 3.0f);
        }
    };
    auto STORE = [&](int buf) {
        uint4 h0, l0, h1, l1;
        split8(v, h0, l0);
        split8(v + 8, h1, l1);
        char* base = smem + (isSelf ? L_ASELF(buf) : L_ANEI(buf))
                   + (size_t)(r * RSA + cq) * 2;
        *(uint4*)(base)             = h0;
        *(uint4*)(base + 16)        = h1;
        *(uint4*)(base + 9216)      = l0;
        *(uint4*)(base + 9216 + 16) = l1;
    };

    float d[2][4][4];
#pragma unroll
    for (int i = 0; i < 2; ++i)
#pragma unroll
        for (int j = 0; j < 4; ++j)
#pragma unroll
            for (int k = 0; k < 4; ++k) d[i][j][k] = 0.f;

    ISSUE_W(0, 0);
    CP_COMMIT();
    PREF(0);
    STORE(0);
    CP_WAIT0();
    __syncthreads();

#pragma unroll
    for (int ch = 0; ch < 4; ++ch) {
        const int cb = ch & 1, nb = cb ^ 1;
        if (ch < 3) {
            ISSUE_W(ch + 1, nb);
            CP_COMMIT();
            PREF(ch + 1);
        }
        const uint32_t aB = sb + (wn < 4 ? L_ASELF(cb) : L_ANEI(cb));
        const uint32_t aH = aB, aL = aB + 9216;
        const uint32_t wH = sb + L_W(cb), wL = wH + 36864;
#pragma unroll
        for (int ks = 0; ks < 4; ++ks) {
            uint32_t ah[2][4], al[2][4];
#pragma unroll
            for (int mi = 0; mi < 2; ++mi) {
                uint32_t ad = (uint32_t)((wm * 32 + mi * 16 + aro) * RSA
                                         + ks * 16 + aco) * 2;
                ldmx4(ah[mi], aH + ad);
                ldmx4(al[mi], aL + ad);
            }
            uint32_t bh[4][2], bl[4][2];
#pragma unroll
            for (int nip = 0; nip < 2; ++nip) {
                uint32_t bd = (uint32_t)((wn * 32 + nip * 16 + bro) * RSA
                                         + ks * 16 + bco) * 2;
                uint32_t t4[4];
                ldmx4(t4, wH + bd);
                bh[2 * nip][0] = t4[0]; bh[2 * nip][1] = t4[1];
                bh[2 * nip + 1][0] = t4[2]; bh[2 * nip + 1][1] = t4[3];
                ldmx4(t4, wL + bd);
                bl[2 * nip][0] = t4[0]; bl[2 * nip][1] = t4[1];
                bl[2 * nip + 1][0] = t4[2]; bl[2 * nip + 1][1] = t4[3];
            }
#pragma unroll
            for (int ni = 0; ni < 4; ++ni)
#pragma unroll
                for (int mi = 0; mi < 2; ++mi) {
                    mma16816(d[mi][ni], ah[mi], bh[ni][0], bh[ni][1]);
                    mma16816(d[mi][ni], ah[mi], bl[ni][0], bl[ni][1]);
                    mma16816(d[mi][ni], al[mi], bh[ni][0], bh[ni][1]);
                }
        }
        if (ch < 3) {
            STORE(nb);
            CP_WAIT0();
        }
        __syncthreads();
    }

    // ---- issue fc W loads (hidden under epilogue math) -----------------------
#pragma unroll
    for (int i = 0; i < 16; ++i) {
        int o = tid + i * 512;
        int plane = o >> 12, ix = o & 4095;
        int row = ix >> 5, c8 = (ix & 31) * 8;
        const __nv_bfloat16* src = (plane ? fc_lo : fc_hi) + (size_t)row * 256 + c8;
        cp16(sb + L_FCH + (plane ? 67584 : 0) + (uint32_t)(row * RSH + c8) * 2, src);
    }
    CP_COMMIT();

    // ---- epilogue: bias + relu + row sum-of-squares --------------------------
    float* ss = (float*)(smem + L_SS);
    if (tid < 64) ss[tid] = 0.f;
    __syncthreads();

#pragma unroll
    for (int mi = 0; mi < 2; ++mi) {
        const int r0 = wm * 32 + mi * 16 + lr;
        float s0 = 0.f, s1 = 0.f;
#pragma unroll
        for (int ni = 0; ni < 4; ++ni) {
            const int col = wn * 32 + ni * 8 + lc;
            const float b0 = (col < 128) ? bS[col] : bN[col - 128];
            const float b1 = (col + 1 < 128) ? bS[col + 1] : bN[col - 127];
            d[mi][ni][0] = fmaxf(d[mi][ni][0] + b0, 0.f);
            d[mi][ni][1] = fmaxf(d[mi][ni][1] + b1, 0.f);
            d[mi][ni][2] = fmaxf(d[mi][ni][2] + b0, 0.f);
            d[mi][ni][3] = fmaxf(d[mi][ni][3] + b1, 0.f);
            s0 += d[mi][ni][0] * d[mi][ni][0] + d[mi][ni][1] * d[mi][ni][1];
            s1 += d[mi][ni][2] * d[mi][ni][2] + d[mi][ni][3] * d[mi][ni][3];
        }
        s0 += __shfl_xor_sync(0xffffffffu, s0, 1);
        s0 += __shfl_xor_sync(0xffffffffu, s0, 2);
        s1 += __shfl_xor_sync(0xffffffffu, s1, 1);
        s1 += __shfl_xor_sync(0xffffffffu, s1, 2);
        if ((lane & 3) == 0) {
            atomicAdd(&ss[r0], s0);
            atomicAdd(&ss[r0 + 8], s1);
        }
    }
    __syncthreads();

    // scale + split -> h tiles (reuse stage-1 A region)
#pragma unroll
    for (int mi = 0; mi < 2; ++mi) {
        const int r0 = wm * 32 + mi * 16 + lr;
        const float sc0 = 1.0f / fmaxf(sqrtf(ss[r0]), 1e-12f);
        const float sc1 = 1.0f / fmaxf(sqrtf(ss[r0 + 8]), 1e-12f);
#pragma unroll
        for (int ni = 0; ni < 4; ++ni) {
            const int col = wn * 32 + ni * 8 + lc;
            uint32_t h, l;
            split2(d[mi][ni][0] * sc0, d[mi][ni][1] * sc0, h, l);
            *(uint32_t*)(smem + L_HH + (size_t)(r0 * RSH + col) * 2) = h;
            *(uint32_t*)(smem + L_HL + (size_t)(r0 * RSH + col) * 2) = l;
            split2(d[mi][ni][2] * sc1, d[mi][ni][3] * sc1, h, l);
            *(uint32_t*)(smem + L_HH + (size_t)((r0 + 8) * RSH + col) * 2) = h;
            *(uint32_t*)(smem + L_HL + (size_t)((r0 + 8) * RSH + col) * 2) = l;
        }
    }
    CP_WAIT0();
    __syncthreads();

    // ---- stage 2: out = h @ fc^T  (M=64, N=128, K=256), warp 32x16 ----------
    const int wm2 = wid & 1, wn2 = wid >> 1;        // 2m x 8n
    float e[2][2][4];
#pragma unroll
    for (int i = 0; i < 2; ++i)
#pragma unroll
        for (int j = 0; j < 2; ++j)
#pragma unroll
            for (int k = 0; k < 4; ++k) e[i][j][k] = 0.f;

#pragma unroll
    for (int ks = 0; ks < 16; ++ks) {
        uint32_t ah[2][4], al[2][4];
#pragma unroll
        for (int mi = 0; mi < 2; ++mi) {
            uint32_t ad = (uint32_t)((wm2 * 32 + mi * 16 + aro) * RSH
                                     + ks * 16 + aco) * 2;
            ldmx4(ah[mi], sb + L_HH + ad);
            ldmx4(al[mi], sb + L_HL + ad);
        }
        uint32_t bd = (uint32_t)((wn2 * 16 + bro) * RSH + ks * 16 + bco) * 2;
        uint32_t th[4], tl[4];
        ldmx4(th, sb + L_FCH + bd);
        ldmx4(tl, sb + L_FCL + bd);
#pragma unroll
        for (int ni = 0; ni < 2; ++ni) {
            const uint32_t bh0 = th[2 * ni], bh1 = th[2 * ni + 1];
            const uint32_t bl0 = tl[2 * ni], bl1 = tl[2 * ni + 1];
#pragma unroll
            for (int mi = 0; mi < 2; ++mi) {
                mma16816(e[mi][ni], ah[mi], bh0, bh1);
                mma16816(e[mi][ni], ah[mi], bl0, bl1);
                mma16816(e[mi][ni], al[mi], bh0, bh1);
            }
        }
    }

#pragma unroll
    for (int mi = 0; mi < 2; ++mi) {
        const int row = m0 + wm2 * 32 + mi * 16 + lr;
#pragma unroll
        for (int ni = 0; ni < 2; ++ni) {
            const int col = wn2 * 16 + ni * 8 + lc;
            const float b0 = __ldg(&fcb[col]), b1 = __ldg(&fcb[col + 1]);
            *(float2*)(out + (size_t)row * 128 + col) =
                make_float2(e[mi][ni][0] + b0, e[mi][ni][1] + b1);
            *(float2*)(out + (size_t)(row + 8) * 128 + col) =
                make_float2(e[mi][ni][2] + b0, e[mi][ni][3] + b1);
        }
    }
}

// ---------------------------------------------------------------------------
extern "C" void kernel_launch(void* const* d_in, const int* in_sizes, int n_in,
                              void* d_out, int out_size)
{
    const float* emb      = (const float*)d_in[0];
    const float* w_self0  = (const float*)d_in[1];
    const float* b_self0  = (const float*)d_in[2];
    const float* w_neigh0 = (const float*)d_in[3];
    const float* b_neigh0 = (const float*)d_in[4];
    const float* w_self1  = (const float*)d_in[5];
    const float* b_self1  = (const float*)d_in[6];
    const float* w_neigh1 = (const float*)d_in[7];
    const float* b_neigh1 = (const float*)d_in[8];
    const float* fc_w     = (const float*)d_in[9];
    const float* fc_b     = (const float*)d_in[10];
    const int*   nodeids  = (const int*)d_in[11];
    const int*   neigh1   = (const int*)d_in[12];
    const int*   neigh2   = (const int*)d_in[13];
    float*       out      = (float*)d_out;

    __nv_bfloat16 *WHI, *WLO;
    float *F0, *F1;
    cudaGetSymbolAddress((void**)&WHI, g_whi);
    cudaGetSymbolAddress((void**)&WLO, g_wlo);
    cudaGetSymbolAddress((void**)&F0, g_F0);
    cudaGetSymbolAddress((void**)&F1, g_F1);

    cudaFuncSetAttribute(layer0_k, cudaFuncAttributeMaxDynamicSharedMemorySize, G_SMEM);
    cudaFuncSetAttribute(l1fc_k,   cudaFuncAttributeMaxDynamicSharedMemorySize, L_SMEM);

    conv_w<<<160, 256>>>(w_self0, w_neigh0, w_self1, w_neigh1, fc_w, WHI, WLO);

    layer0_k<<<2048, 256, G_SMEM>>>(emb, nodeids, neigh1, neigh2,
                                    WHI, WLO, b_self0, b_neigh0, F0, F1);

    l1fc_k<<<B_ROOT / 64, 512, L_SMEM>>>(F0, F1,
                                         WHI + 65536, WLO + 65536,
                                         b_self1, b_neigh1,
                                         WHI + 131072, WLO + 131072,
                                         fc_b, out);
}

// round 11
// speedup vs baseline: 1.2312x; 1.0001x over previous
#include <cuda_runtime.h>
#include <cuda_bf16.h>
#include <cstdint>

// ---------------------------------------------------------------------------
// GraphSAGE, mma.sync bf16 hi/lo (3-product fp32-accurate).
// layer0_k: weight pre-split fused in (first 8 CTAs convert, spin-flag), then
//   4 GEMM segments in one launch; gemm_body = CTA 256 thr, M64 x N128,
//   K=256 in 4 chunks, A gather->regs(batched)->split->SMEM, W cp.async
//   dbl-buffered, 108 KB SMEM -> 2 CTAs/SM.
// l1fc_k: 512 thr, M64 x N256 layer-1 tile + row L2-norm + FC fused;
//   also resets the weight-flag for the next graph replay.
// ---------------------------------------------------------------------------

#define B_ROOT 16384
#define R1     49152
#define RSA    72            // chunk tile row stride (bf16 elems)
#define RSH    264           // l1fc h / fc row stride

// gemm smem (bytes)
#define GA(b)  ((b) * 18432)                 // A: hi +0, lo +9216
#define GW(b)  (36864 + (b) * 36864)         // W: hi +0, lo +18432
#define G_SMEM 110592
// l1fc smem (bytes)
#define L_ASELF(b) ((b) * 36864)             // self A: hi +0, lo +9216
#define L_ANEI(b)  ((b) * 36864 + 18432)     // neigh A: hi +0, lo +9216
#define L_W(b)     (73728 + (b) * 73728)     // W(256 rows): hi +0, lo +36864
#define L_SMEM     221184
// stage-2 aliases (reused after stage-1 drains)
#define L_HH  0
#define L_HL  33792
#define L_SS  67584
#define L_FCH 73728
#define L_FCL 141312

// ---------------- scratch ----------------------------------------------------
__device__ float g_F0[B_ROOT * 256];
__device__ float g_F1[R1 * 256];
__device__ __nv_bfloat16 g_whi[5 * 32768];
__device__ __nv_bfloat16 g_wlo[5 * 32768];
__device__ unsigned g_wflag;     // converters-done counter (reset by l1fc_k)

// ---------------- helpers ----------------------------------------------------
__device__ __forceinline__ uint32_t smem_u32(const void* p) {
    uint32_t a;
    asm("{ .reg .u64 t; cvta.to.shared.u64 t, %1; cvt.u32.u64 %0, t; }"
        : "=r"(a) : "l"(p));
    return a;
}
__device__ __forceinline__ void split2(float a, float b, uint32_t& h, uint32_t& l) {
    __nv_bfloat16 ah = __float2bfloat16_rn(a), bh = __float2bfloat16_rn(b);
    __nv_bfloat16 al = __float2bfloat16_rn(a - __bfloat162float(ah));
    __nv_bfloat16 bl = __float2bfloat16_rn(b - __bfloat162float(bh));
    __nv_bfloat162 ph = __halves2bfloat162(ah, bh);
    __nv_bfloat162 pl = __halves2bfloat162(al, bl);
    h = *reinterpret_cast<uint32_t*>(&ph);
    l = *reinterpret_cast<uint32_t*>(&pl);
}
__device__ __forceinline__ void split8(const float* v, uint4& h4, uint4& l4) {
    uint32_t h[4], l[4];
#pragma unroll
    for (int i = 0; i < 4; ++i) split2(v[2 * i], v[2 * i + 1], h[i], l[i]);
    h4 = make_uint4(h[0], h[1], h[2], h[3]);
    l4 = make_uint4(l[0], l[1], l[2], l[3]);
}
__device__ __forceinline__ void mma16816(float* d, const uint32_t* a,
                                         uint32_t b0, uint32_t b1) {
    asm volatile(
        "mma.sync.aligned.m16n8k16.row.col.f32.bf16.bf16.f32 "
        "{%0,%1,%2,%3}, {%4,%5,%6,%7}, {%8,%9}, {%0,%1,%2,%3};"
        : "+f"(d[0]), "+f"(d[1]), "+f"(d[2]), "+f"(d[3])
        : "r"(a[0]), "r"(a[1]), "r"(a[2]), "r"(a[3]), "r"(b0), "r"(b1));
}
__device__ __forceinline__ void ldmx4(uint32_t* r, uint32_t a) {
    asm volatile("ldmatrix.sync.aligned.m8n8.x4.shared.b16 {%0,%1,%2,%3}, [%4];"
                 : "=r"(r[0]), "=r"(r[1]), "=r"(r[2]), "=r"(r[3]) : "r"(a));
}
__device__ __forceinline__ void cp16(uint32_t dst, const void* src) {
    asm volatile("cp.async.cg.shared.global [%0], [%1], 16;" :: "r"(dst), "l"(src));
}
#define CP_COMMIT() asm volatile("cp.async.commit_group;" ::: "memory")
#define CP_WAIT0()  asm volatile("cp.async.wait_group 0;"  ::: "memory")

// ---------------- layer-0 GEMM body --------------------------------------------
// GATHER: 0 = A[idx[m]], 1 = mean_{j<KF} A[idx[m*KF+j]]
template <int GATHER, int KF>
__device__ __forceinline__ void
gemm_body(char* smem, const float* __restrict__ A, const int* __restrict__ idx,
          const __nv_bfloat16* __restrict__ w_hi, const __nv_bfloat16* __restrict__ w_lo,
          const float* __restrict__ bias,
          float* __restrict__ C, int ldc, int col_off, int m0)
{
    const uint32_t sb = smem_u32(smem);
    const int tid = threadIdx.x, lane = tid & 31, wid = tid >> 5;
    const int wm = wid >> 2, wn = wid & 3;
    const int lr = lane >> 2, lc = (lane & 3) * 2;
    const int g  = lane >> 3, lm = lane & 7;
    const int aro = ((g & 1) << 3) + lm, aco = (g >> 1) << 3;
    const int bro = ((g >> 1) << 3) + lm, bco = (g & 1) << 3;
    const int r  = tid >> 2, cq = (tid & 3) * 16;

    auto ISSUE_W = [&](int ch, int buf) {
        const int kb = ch * 64;
#pragma unroll
        for (int i = 0; i < 8; ++i) {
            int o = tid + i * 256;
            int plane = o >> 10, ix = o & 1023;
            int row = ix >> 3, c8 = (ix & 7) * 8;
            const __nv_bfloat16* src =
                (plane ? w_lo : w_hi) + (size_t)row * 256 + kb + c8;
            cp16(sb + GW(buf) + (plane ? 18432 : 0)
                 + (uint32_t)(row * RSA + c8) * 2, src);
        }
    };

    int rows[KF];
    if (GATHER == 0)      rows[0] = idx[m0 + r];
    else {
#pragma unroll
        for (int j = 0; j < KF; ++j) rows[j] = idx[(size_t)(m0 + r) * KF + j];
    }

    float v[16];
    auto PREF = [&](int ch) {
        const int kb = ch * 64;
        if (GATHER == 0) {
            const float4* p = (const float4*)(A + (size_t)rows[0] * 256 + kb + cq);
            float4 t0 = __ldg(p), t1 = __ldg(p + 1), t2 = __ldg(p + 2), t3 = __ldg(p + 3);
            v[0]  = t0.x; v[1]  = t0.y; v[2]  = t0.z; v[3]  = t0.w;
            v[4]  = t1.x; v[5]  = t1.y; v[6]  = t1.z; v[7]  = t1.w;
            v[8]  = t2.x; v[9]  = t2.y; v[10] = t2.z; v[11] = t2.w;
            v[12] = t3.x; v[13] = t3.y; v[14] = t3.z; v[15] = t3.w;
        } else {
#pragma unroll
            for (int i = 0; i < 16; ++i) v[i] = 0.f;
#pragma unroll
            for (int h = 0; h < 2; ++h) {          // two 8-float halves
                float4 t[2 * KF];                  // independent loads -> high MLP
#pragma unroll
                for (int j = 0; j < KF; ++j) {
                    const float4* p = (const float4*)(A + (size_t)rows[j] * 256
                                                      + kb + cq + h * 8);
                    t[j * 2]     = __ldg(p);
                    t[j * 2 + 1] = __ldg(p + 1);
                }
#pragma unroll
                for (int j = 0; j < KF; ++j)
#pragma unroll
                    for (int q = 0; q < 2; ++q) {
                        const float4 f = t[j * 2 + q];
                        const int o = h * 8 + q * 4;
                        v[o + 0] += f.x; v[o + 1] += f.y;
                        v[o + 2] += f.z; v[o + 3] += f.w;
                    }
            }
        }
    };
    auto STORE = [&](int buf) {
        const float s = 1.0f / (float)KF;
        float w[16];
#pragma unroll
        for (int i = 0; i < 16; ++i) w[i] = v[i] * s;
        uint4 h0, l0, h1, l1;
        split8(w, h0, l0);
        split8(w + 8, h1, l1);
        char* base = smem + GA(buf) + (size_t)(r * RSA + cq) * 2;
        *(uint4*)(base)              = h0;
        *(uint4*)(base + 16)         = h1;
        *(uint4*)(base + 9216)       = l0;
        *(uint4*)(base + 9216 + 16)  = l1;
    };

    float d[2][4][4];
#pragma unroll
    for (int i = 0; i < 2; ++i)
#pragma unroll
        for (int j = 0; j < 4; ++j)
#pragma unroll
            for (int k = 0; k < 4; ++k) d[i][j][k] = 0.f;

    ISSUE_W(0, 0);
    CP_COMMIT();
    PREF(0);
    STORE(0);
    CP_WAIT0();
    __syncthreads();

#pragma unroll
    for (int ch = 0; ch < 4; ++ch) {
        const int cb = ch & 1, nb = cb ^ 1;
        if (ch < 3) {
            ISSUE_W(ch + 1, nb);
            CP_COMMIT();
            PREF(ch + 1);
        }
        const uint32_t aH = sb + GA(cb), aL = aH + 9216;
        const uint32_t wH = sb + GW(cb), wL = wH + 18432;
#pragma unroll
        for (int ks = 0; ks < 4; ++ks) {
            uint32_t ah[2][4], al[2][4];
#pragma unroll
            for (int mi = 0; mi < 2; ++mi) {
                uint32_t ad = (uint32_t)((wm * 32 + mi * 16 + aro) * RSA
                                         + ks * 16 + aco) * 2;
                ldmx4(ah[mi], aH + ad);
                ldmx4(al[mi], aL + ad);
            }
            uint32_t bh[4][2], bl[4][2];
#pragma unroll
            for (int nip = 0; nip < 2; ++nip) {
                uint32_t bd = (uint32_t)((wn * 32 + nip * 16 + bro) * RSA
                                         + ks * 16 + bco) * 2;
                uint32_t t4[4];
                ldmx4(t4, wH + bd);
                bh[2 * nip][0] = t4[0]; bh[2 * nip][1] = t4[1];
                bh[2 * nip + 1][0] = t4[2]; bh[2 * nip + 1][1] = t4[3];
                ldmx4(t4, wL + bd);
                bl[2 * nip][0] = t4[0]; bl[2 * nip][1] = t4[1];
                bl[2 * nip + 1][0] = t4[2]; bl[2 * nip + 1][1] = t4[3];
            }
#pragma unroll
            for (int ni = 0; ni < 4; ++ni)
#pragma unroll
                for (int mi = 0; mi < 2; ++mi) {
                    mma16816(d[mi][ni], ah[mi], bh[ni][0], bh[ni][1]);
                    mma16816(d[mi][ni], ah[mi], bl[ni][0], bl[ni][1]);
                    mma16816(d[mi][ni], al[mi], bh[ni][0], bh[ni][1]);
                }
        }
        if (ch < 3) {
            STORE(nb);
            CP_WAIT0();
        }
        __syncthreads();
    }

#pragma unroll
    for (int mi = 0; mi < 2; ++mi) {
        const int row = m0 + wm * 32 + mi * 16 + lr;
#pragma unroll
        for (int ni = 0; ni < 4; ++ni) {
            const int col = wn * 32 + ni * 8 + lc;
            const float b0 = __ldg(&bias[col]), b1 = __ldg(&bias[col + 1]);
            *(float2*)(C + (size_t)row * ldc + col_off + col) =
                make_float2(fmaxf(d[mi][ni][0] + b0, 0.f),
                            fmaxf(d[mi][ni][1] + b1, 0.f));
            *(float2*)(C + (size_t)(row + 8) * ldc + col_off + col) =
                make_float2(fmaxf(d[mi][ni][2] + b0, 0.f),
                            fmaxf(d[mi][ni][3] + b1, 0.f));
        }
    }
}

// ---------------- layer 0: fused weight-split + 4 GEMM segments ------------------
// bids 0..7 convert weights first (they are wave-1 resident; others acquire-spin).
// bid [0,768)    : F1 neigh = mean5 emb[neigh2]  @ Wn0
// bid [768,1536) : F1 self  = emb[neigh1]        @ Ws0
// bid [1536,1792): F0 neigh = mean3 emb[neigh1]  @ Wn0
// bid [1792,2048): F0 self  = emb[nodeids]       @ Ws0
__global__ void __launch_bounds__(256, 2)
layer0_k(const float* __restrict__ emb,
         const int* __restrict__ nodeids, const int* __restrict__ neigh1,
         const int* __restrict__ neigh2,
         const float* __restrict__ ws0, const float* __restrict__ wn0,
         const float* __restrict__ ws1, const float* __restrict__ wn1,
         const float* __restrict__ fcw,
         __nv_bfloat16* __restrict__ whi_o, __nv_bfloat16* __restrict__ wlo_o,
         const __nv_bfloat16* __restrict__ whi, const __nv_bfloat16* __restrict__ wlo,
         const float* __restrict__ bs0, const float* __restrict__ bn0,
         float* __restrict__ F0, float* __restrict__ F1)
{
    extern __shared__ char smem[];
    const int bid = blockIdx.x;
    const int tid = threadIdx.x;

    // ---- converter segment: 8 CTAs x 256 thr x 20 float4 = 163840 floats -----
    if (bid < 8) {
        const float* src[5] = {ws0, wn0, ws1, wn1, fcw};
#pragma unroll
        for (int i = 0; i < 20; ++i) {
            int idx4 = bid * 5120 + i * 256 + tid;   // float4 index, 40960 total
            int base = idx4 * 4;
            float4 f = __ldg((const float4*)(src[base >> 15] + (base & 32767)));
            uint32_t h0, l0, h1, l1;
            split2(f.x, f.y, h0, l0);
            split2(f.z, f.w, h1, l1);
            *(uint2*)(whi_o + base) = make_uint2(h0, h1);
            *(uint2*)(wlo_o + base) = make_uint2(l0, l1);
        }
        __syncthreads();
        if (tid == 0) {
            unsigned old;
            asm volatile("atom.add.release.gpu.u32 %0, [%1], 1;"
                         : "=r"(old) : "l"(&g_wflag) : "memory");
        }
    }
    // ---- all CTAs: wait for the 8 converters ---------------------------------
    if (tid == 0) {
        unsigned val;
        do {
            asm volatile("ld.acquire.gpu.u32 %0, [%1];"
                         : "=r"(val) : "l"(&g_wflag) : "memory");
            if (val >= 8u) break;
            __nanosleep(64);
        } while (true);
    }
    __syncthreads();

    // ---- GEMM segments --------------------------------------------------------
    if (bid < 768) {
        gemm_body<1, 5>(smem, emb, neigh2, whi + 32768, wlo + 32768, bn0,
                        F1, 256, 128, bid * 64);
    } else if (bid < 1536) {
        gemm_body<0, 1>(smem, emb, neigh1, whi, wlo, bs0,
                        F1, 256, 0, (bid - 768) * 64);
    } else if (bid < 1792) {
        gemm_body<1, 3>(smem, emb, neigh1, whi + 32768, wlo + 32768, bn0,
                        F0, 256, 128, (bid - 1536) * 64);
    } else {
        gemm_body<0, 1>(smem, emb, nodeids, whi, wlo, bs0,
                        F0, 256, 0, (bid - 1792) * 64);
    }
}

// ---------------- fused layer1 + L2-norm + FC -----------------------------------
__global__ void __launch_bounds__(512, 1)
l1fc_k(const float* __restrict__ F0, const float* __restrict__ F1,
       const __nv_bfloat16* __restrict__ w1_hi, const __nv_bfloat16* __restrict__ w1_lo,
       const float* __restrict__ bS, const float* __restrict__ bN,
       const __nv_bfloat16* __restrict__ fc_hi, const __nv_bfloat16* __restrict__ fc_lo,
       const float* __restrict__ fcb, float* __restrict__ out)
{
    extern __shared__ char smem[];
    const uint32_t sb = smem_u32(smem);
    const int tid = threadIdx.x, lane = tid & 31, wid = tid >> 5;
    const int wm = wid >> 3, wn = wid & 7;          // stage1: 2m x 8n, warp 32x32
    const int lr = lane >> 2, lc = (lane & 3) * 2;
    const int g  = lane >> 3, lm = lane & 7;
    const int aro = ((g & 1) << 3) + lm, aco = (g >> 1) << 3;
    const int bro = ((g >> 1) << 3) + lm, bco = (g & 1) << 3;
    const int m0 = blockIdx.x * 64;

    // reset weight-flag for the next graph replay (layer0 of THIS replay is done)
    if (blockIdx.x == 0 && tid == 0) {
        asm volatile("st.relaxed.gpu.u32 [%0], 0;" :: "l"(&g_wflag) : "memory");
    }

    const bool isSelf = tid < 256;
    const int lt = tid & 255;
    const int r = lt >> 2, cq = (lt & 3) * 16;

    auto ISSUE_W = [&](int ch, int buf) {
        const int kb = ch * 64;
#pragma unroll
        for (int i = 0; i < 8; ++i) {
            int o = tid + i * 512;
            int plane = o >> 11, ix = o & 2047;
            int row = ix >> 3, c8 = (ix & 7) * 8;
            const __nv_bfloat16* src =
                (plane ? w1_lo : w1_hi) + (size_t)row * 256 + kb + c8;
            cp16(sb + L_W(buf) + (plane ? 36864 : 0)
                 + (uint32_t)(row * RSA + c8) * 2, src);
        }
    };

    float v[16];
    auto PREF = [&](int ch) {
        const int kb = ch * 64;
        if (isSelf) {
            const float4* p = (const float4*)(F0 + (size_t)(m0 + r) * 256 + kb + cq);
            float4 t0 = __ldg(p), t1 = __ldg(p + 1), t2 = __ldg(p + 2), t3 = __ldg(p + 3);
            v[0]  = t0.x; v[1]  = t0.y; v[2]  = t0.z; v[3]  = t0.w;
            v[4]  = t1.x; v[5]  = t1.y; v[6]  = t1.z; v[7]  = t1.w;
            v[8]  = t2.x; v[9]  = t2.y; v[10] = t2.z; v[11] = t2.w;
            v[12] = t3.x; v[13] = t3.y; v[14] = t3.z; v[15] = t3.w;
        } else {
#pragma unroll
            for (int i = 0; i < 16; ++i) v[i] = 0.f;
#pragma unroll
            for (int h = 0; h < 2; ++h) {
                float4 t[6];
#pragma unroll
                for (int j = 0; j < 3; ++j) {
                    const float4* p = (const float4*)(F1
                        + (size_t)((m0 + r) * 3 + j) * 256 + kb + cq + h * 8);
                    t[j * 2]     = __ldg(p);
                    t[j * 2 + 1] = __ldg(p + 1);
                }
#pragma unroll
                for (int j = 0; j < 3; ++j)
#pragma unroll
                    for (int q = 0; q < 2; ++q) {
                        const float4 f = t[j * 2 + q];
                        const int o = h * 8 + q * 4;
                        v[o + 0] += f.x; v[o + 1] += f.y;
                        v[o + 2] += f.z; v[o + 3] += f.w;
                    }
            }
#pragma unroll
            for (int i = 0; i < 16; ++i) v[i] *= (1.0f / 3.0f);
        }
    };
    auto STORE = [&](int buf) {
        uint4 h0, l0, h1, l1;
        split8(v, h0, l0);
        split8(v + 8, h1, l1);
        char* base = smem + (isSelf ? L_ASELF(buf) : L_ANEI(buf))
                   + (size_t)(r * RSA + cq) * 2;
        *(uint4*)(base)             = h0;
        *(uint4*)(base + 16)        = h1;
        *(uint4*)(base + 9216)      = l0;
        *(uint4*)(base + 9216 + 16) = l1;
    };

    float d[2][4][4];
#pragma unroll
    for (int i = 0; i < 2; ++i)
#pragma unroll
        for (int j = 0; j < 4; ++j)
#pragma unroll
            for (int k = 0; k < 4; ++k) d[i][j][k] = 0.f;

    ISSUE_W(0, 0);
    CP_COMMIT();
    PREF(0);
    STORE(0);
    CP_WAIT0();
    __syncthreads();

#pragma unroll
    for (int ch = 0; ch < 4; ++ch) {
        const int cb = ch & 1, nb = cb ^ 1;
        if (ch < 3) {
            ISSUE_W(ch + 1, nb);
            CP_COMMIT();
            PREF(ch + 1);
        }
        const uint32_t aB = sb + (wn < 4 ? L_ASELF(cb) : L_ANEI(cb));
        const uint32_t aH = aB, aL = aB + 9216;
        const uint32_t wH = sb + L_W(cb), wL = wH + 36864;
#pragma unroll
        for (int ks = 0; ks < 4; ++ks) {
            uint32_t ah[2][4], al[2][4];
#pragma unroll
            for (int mi = 0; mi < 2; ++mi) {
                uint32_t ad = (uint32_t)((wm * 32 + mi * 16 + aro) * RSA
                                         + ks * 16 + aco) * 2;
                ldmx4(ah[mi], aH + ad);
                ldmx4(al[mi], aL + ad);
            }
            uint32_t bh[4][2], bl[4][2];
#pragma unroll
            for (int nip = 0; nip < 2; ++nip) {
                uint32_t bd = (uint32_t)((wn * 32 + nip * 16 + bro) * RSA
                                         + ks * 16 + bco) * 2;
                uint32_t t4[4];
                ldmx4(t4, wH + bd);
                bh[2 * nip][0] = t4[0]; bh[2 * nip][1] = t4[1];
                bh[2 * nip + 1][0] = t4[2]; bh[2 * nip + 1][1] = t4[3];
                ldmx4(t4, wL + bd);
                bl[2 * nip][0] = t4[0]; bl[2 * nip][1] = t4[1];
                bl[2 * nip + 1][0] = t4[2]; bl[2 * nip + 1][1] = t4[3];
            }
#pragma unroll
            for (int ni = 0; ni < 4; ++ni)
#pragma unroll
                for (int mi = 0; mi < 2; ++mi) {
                    mma16816(d[mi][ni], ah[mi], bh[ni][0], bh[ni][1]);
                    mma16816(d[mi][ni], ah[mi], bl[ni][0], bl[ni][1]);
                    mma16816(d[mi][ni], al[mi], bh[ni][0], bh[ni][1]);
                }
        }
        if (ch < 3) {
            STORE(nb);
            CP_WAIT0();
        }
        __syncthreads();
    }

    // ---- issue fc W loads (hidden under epilogue math) -----------------------
#pragma unroll
    for (int i = 0; i < 16; ++i) {
        int o = tid + i * 512;
        int plane = o >> 12, ix = o & 4095;
        int row = ix >> 5, c8 = (ix & 31) * 8;
        const __nv_bfloat16* src = (plane ? fc_lo : fc_hi) + (size_t)row * 256 + c8;
        cp16(sb + L_FCH + (plane ? 67584 : 0) + (uint32_t)(row * RSH + c8) * 2, src);
    }
    CP_COMMIT();

    // ---- epilogue: bias + relu + row sum-of-squares --------------------------
    float* ss = (float*)(smem + L_SS);
    if (tid < 64) ss[tid] = 0.f;
    __syncthreads();

#pragma unroll
    for (int mi = 0; mi < 2; ++mi) {
        const int r0 = wm * 32 + mi * 16 + lr;
        float s0 = 0.f, s1 = 0.f;
#pragma unroll
        for (int ni = 0; ni < 4; ++ni) {
            const int col = wn * 32 + ni * 8 + lc;
            const float b0 = (col < 128) ? bS[col] : bN[col - 128];
            const float b1 = (col + 1 < 128) ? bS[col + 1] : bN[col - 127];
            d[mi][ni][0] = fmaxf(d[mi][ni][0] + b0, 0.f);
            d[mi][ni][1] = fmaxf(d[mi][ni][1] + b1, 0.f);
            d[mi][ni][2] = fmaxf(d[mi][ni][2] + b0, 0.f);
            d[mi][ni][3] = fmaxf(d[mi][ni][3] + b1, 0.f);
            s0 += d[mi][ni][0] * d[mi][ni][0] + d[mi][ni][1] * d[mi][ni][1];
            s1 += d[mi][ni][2] * d[mi][ni][2] + d[mi][ni][3] * d[mi][ni][3];
        }
        s0 += __shfl_xor_sync(0xffffffffu, s0, 1);
        s0 += __shfl_xor_sync(0xffffffffu, s0, 2);
        s1 += __shfl_xor_sync(0xffffffffu, s1, 1);
        s1 += __shfl_xor_sync(0xffffffffu, s1, 2);
        if ((lane & 3) == 0) {
            atomicAdd(&ss[r0], s0);
            atomicAdd(&ss[r0 + 8], s1);
        }
    }
    __syncthreads();

    // scale + split -> h tiles (reuse stage-1 A region)
#pragma unroll
    for (int mi = 0; mi < 2; ++mi) {
        const int r0 = wm * 32 + mi * 16 + lr;
        const float sc0 = 1.0f / fmaxf(sqrtf(ss[r0]), 1e-12f);
        const float sc1 = 1.0f / fmaxf(sqrtf(ss[r0 + 8]), 1e-12f);
#pragma unroll
        for (int ni = 0; ni < 4; ++ni) {
            const int col = wn * 32 + ni * 8 + lc;
            uint32_t h, l;
            split2(d[mi][ni][0] * sc0, d[mi][ni][1] * sc0, h, l);
            *(uint32_t*)(smem + L_HH + (size_t)(r0 * RSH + col) * 2) = h;
            *(uint32_t*)(smem + L_HL + (size_t)(r0 * RSH + col) * 2) = l;
            split2(d[mi][ni][2] * sc1, d[mi][ni][3] * sc1, h, l);
            *(uint32_t*)(smem + L_HH + (size_t)((r0 + 8) * RSH + col) * 2) = h;
            *(uint32_t*)(smem + L_HL + (size_t)((r0 + 8) * RSH + col) * 2) = l;
        }
    }
    CP_WAIT0();
    __syncthreads();

    // ---- stage 2: out = h @ fc^T  (M=64, N=128, K=256), warp 32x16 ----------
    const int wm2 = wid & 1, wn2 = wid >> 1;        // 2m x 8n
    float e[2][2][4];
#pragma unroll
    for (int i = 0; i < 2; ++i)
#pragma unroll
        for (int j = 0; j < 2; ++j)
#pragma unroll
            for (int k = 0; k < 4; ++k) e[i][j][k] = 0.f;

#pragma unroll
    for (int ks = 0; ks < 16; ++ks) {
        uint32_t ah[2][4], al[2][4];
#pragma unroll
        for (int mi = 0; mi < 2; ++mi) {
            uint32_t ad = (uint32_t)((wm2 * 32 + mi * 16 + aro) * RSH
                                     + ks * 16 + aco) * 2;
            ldmx4(ah[mi], sb + L_HH + ad);
            ldmx4(al[mi], sb + L_HL + ad);
        }
        uint32_t bd = (uint32_t)((wn2 * 16 + bro) * RSH + ks * 16 + bco) * 2;
        uint32_t th[4], tl[4];
        ldmx4(th, sb + L_FCH + bd);
        ldmx4(tl, sb + L_FCL + bd);
#pragma unroll
        for (int ni = 0; ni < 2; ++ni) {
            const uint32_t bh0 = th[2 * ni], bh1 = th[2 * ni + 1];
            const uint32_t bl0 = tl[2 * ni], bl1 = tl[2 * ni + 1];
#pragma unroll
            for (int mi = 0; mi < 2; ++mi) {
                mma16816(e[mi][ni], ah[mi], bh0, bh1);
                mma16816(e[mi][ni], ah[mi], bl0, bl1);
                mma16816(e[mi][ni], al[mi], bh0, bh1);
            }
        }
    }

#pragma unroll
    for (int mi = 0; mi < 2; ++mi) {
        const int row = m0 + wm2 * 32 + mi * 16 + lr;
#pragma unroll
        for (int ni = 0; ni < 2; ++ni) {
            const int col = wn2 * 16 + ni * 8 + lc;
            const float b0 = __ldg(&fcb[col]), b1 = __ldg(&fcb[col + 1]);
            *(float2*)(out + (size_t)row * 128 + col) =
                make_float2(e[mi][ni][0] + b0, e[mi][ni][1] + b1);
            *(float2*)(out + (size_t)(row + 8) * 128 + col) =
                make_float2(e[mi][ni][2] + b0, e[mi][ni][3] + b1);
        }
    }
}

// ---------------------------------------------------------------------------
extern "C" void kernel_launch(void* const* d_in, const int* in_sizes, int n_in,
                              void* d_out, int out_size)
{
    const float* emb      = (const float*)d_in[0];
    const float* w_self0  = (const float*)d_in[1];
    const float* b_self0  = (const float*)d_in[2];
    const float* w_neigh0 = (const float*)d_in[3];
    const float* b_neigh0 = (const float*)d_in[4];
    const float* w_self1  = (const float*)d_in[5];
    const float* b_self1  = (const float*)d_in[6];
    const float* w_neigh1 = (const float*)d_in[7];
    const float* b_neigh1 = (const float*)d_in[8];
    const float* fc_w     = (const float*)d_in[9];
    const float* fc_b     = (const float*)d_in[10];
    const int*   nodeids  = (const int*)d_in[11];
    const int*   neigh1   = (const int*)d_in[12];
    const int*   neigh2   = (const int*)d_in[13];
    float*       out      = (float*)d_out;

    __nv_bfloat16 *WHI, *WLO;
    float *F0, *F1;
    cudaGetSymbolAddress((void**)&WHI, g_whi);
    cudaGetSymbolAddress((void**)&WLO, g_wlo);
    cudaGetSymbolAddress((void**)&F0, g_F0);
    cudaGetSymbolAddress((void**)&F1, g_F1);

    cudaFuncSetAttribute(layer0_k, cudaFuncAttributeMaxDynamicSharedMemorySize, G_SMEM);
    cudaFuncSetAttribute(l1fc_k,   cudaFuncAttributeMaxDynamicSharedMemorySize, L_SMEM);

    layer0_k<<<2048, 256, G_SMEM>>>(emb, nodeids, neigh1, neigh2,
                                    w_self0, w_neigh0, w_self1, w_neigh1, fc_w,
                                    WHI, WLO, WHI, WLO,
                                    b_self0, b_neigh0, F0, F1);

    l1fc_k<<<B_ROOT / 64, 512, L_SMEM>>>(F0, F1,
                                         WHI + 65536, WLO + 65536,
                                         b_self1, b_neigh1,
                                         WHI + 131072, WLO + 131072,
                                         fc_b, out);
}

// round 12
// speedup vs baseline: 1.2666x; 1.0288x over previous
#include <cuda_runtime.h>
#include <cuda_bf16.h>
#include <cstdint>

// ---------------------------------------------------------------------------
// GraphSAGE, mma.sync bf16 hi/lo (3-product fp32-accurate).
// layer0_k: weight pre-split fused (8 converter CTAs + acquire flag), then 4
//   GEMM segments; gemm_body = 256 thr, M64 x N128, K=256 in 4 chunks,
//   A gather->regs->split->SMEM, W cp.async dbl-buffered, 2 CTAs/SM.
// l1fc_k (NEW): 256 thr, 2 CTAs/SM (SMEM 102 KB, regs 256x128x2 = full RF).
//   Stage1 M64 x N256 layer-1 (k32 chunks, A single-buf, W dbl-buf), row
//   L2-norm, stage2 FC (fc chunked single-buf over dead W region).
// ---------------------------------------------------------------------------

#define B_ROOT 16384
#define R1     49152
#define RSA    72            // k64 tile row stride (bf16 elems)
#define RSC    40            // k32 tile row stride (bf16 elems)
#define RSH    264           // h row stride

// layer0 smem (bytes)
#define GA(b)  ((b) * 18432)                 // A: hi +0, lo +9216
#define GW(b)  (36864 + (b) * 36864)         // W: hi +0, lo +18432
#define G_SMEM 110592
// l1fc smem (bytes)
#define C_ASH  0                              // self A hi   [64][40]
#define C_ASL  5120
#define C_ANH  10240
#define C_ANL  15360
#define C_W(b) (20480 + (b) * 40960)          // W buf: hi +0 (20480), lo +20480
#define C_HH   0                              // stage2: h hi [64][264]
#define C_HL   33792
#define C_FC   67584                          // fc buf: hi +0 (18432), lo +18432
#define C_SS   104448                         // float ss[64]
#define L_SMEM 104704

// ---------------- scratch ----------------------------------------------------
__device__ float g_F0[B_ROOT * 256];
__device__ float g_F1[R1 * 256];
__device__ __nv_bfloat16 g_whi[5 * 32768];
__device__ __nv_bfloat16 g_wlo[5 * 32768];
__device__ unsigned g_wflag;

// ---------------- helpers ----------------------------------------------------
__device__ __forceinline__ uint32_t smem_u32(const void* p) {
    uint32_t a;
    asm("{ .reg .u64 t; cvta.to.shared.u64 t, %1; cvt.u32.u64 %0, t; }"
        : "=r"(a) : "l"(p));
    return a;
}
__device__ __forceinline__ void split2(float a, float b, uint32_t& h, uint32_t& l) {
    __nv_bfloat16 ah = __float2bfloat16_rn(a), bh = __float2bfloat16_rn(b);
    __nv_bfloat16 al = __float2bfloat16_rn(a - __bfloat162float(ah));
    __nv_bfloat16 bl = __float2bfloat16_rn(b - __bfloat162float(bh));
    __nv_bfloat162 ph = __halves2bfloat162(ah, bh);
    __nv_bfloat162 pl = __halves2bfloat162(al, bl);
    h = *reinterpret_cast<uint32_t*>(&ph);
    l = *reinterpret_cast<uint32_t*>(&pl);
}
__device__ __forceinline__ void split8(const float* v, uint4& h4, uint4& l4) {
    uint32_t h[4], l[4];
#pragma unroll
    for (int i = 0; i < 4; ++i) split2(v[2 * i], v[2 * i + 1], h[i], l[i]);
    h4 = make_uint4(h[0], h[1], h[2], h[3]);
    l4 = make_uint4(l[0], l[1], l[2], l[3]);
}
__device__ __forceinline__ void mma16816(float* d, const uint32_t* a,
                                         uint32_t b0, uint32_t b1) {
    asm volatile(
        "mma.sync.aligned.m16n8k16.row.col.f32.bf16.bf16.f32 "
        "{%0,%1,%2,%3}, {%4,%5,%6,%7}, {%8,%9}, {%0,%1,%2,%3};"
        : "+f"(d[0]), "+f"(d[1]), "+f"(d[2]), "+f"(d[3])
        : "r"(a[0]), "r"(a[1]), "r"(a[2]), "r"(a[3]), "r"(b0), "r"(b1));
}
__device__ __forceinline__ void ldmx4(uint32_t* r, uint32_t a) {
    asm volatile("ldmatrix.sync.aligned.m8n8.x4.shared.b16 {%0,%1,%2,%3}, [%4];"
                 : "=r"(r[0]), "=r"(r[1]), "=r"(r[2]), "=r"(r[3]) : "r"(a));
}
__device__ __forceinline__ void cp16(uint32_t dst, const void* src) {
    asm volatile("cp.async.cg.shared.global [%0], [%1], 16;" :: "r"(dst), "l"(src));
}
#define CP_COMMIT() asm volatile("cp.async.commit_group;" ::: "memory")
#define CP_WAIT0()  asm volatile("cp.async.wait_group 0;"  ::: "memory")

// ---------------- layer-0 GEMM body (unchanged, proven) ------------------------
template <int GATHER, int KF>
__device__ __forceinline__ void
gemm_body(char* smem, const float* __restrict__ A, const int* __restrict__ idx,
          const __nv_bfloat16* __restrict__ w_hi, const __nv_bfloat16* __restrict__ w_lo,
          const float* __restrict__ bias,
          float* __restrict__ C, int ldc, int col_off, int m0)
{
    const uint32_t sb = smem_u32(smem);
    const int tid = threadIdx.x, lane = tid & 31, wid = tid >> 5;
    const int wm = wid >> 2, wn = wid & 3;
    const int lr = lane >> 2, lc = (lane & 3) * 2;
    const int g  = lane >> 3, lm = lane & 7;
    const int aro = ((g & 1) << 3) + lm, aco = (g >> 1) << 3;
    const int bro = ((g >> 1) << 3) + lm, bco = (g & 1) << 3;
    const int r  = tid >> 2, cq = (tid & 3) * 16;

    auto ISSUE_W = [&](int ch, int buf) {
        const int kb = ch * 64;
#pragma unroll
        for (int i = 0; i < 8; ++i) {
            int o = tid + i * 256;
            int plane = o >> 10, ix = o & 1023;
            int row = ix >> 3, c8 = (ix & 7) * 8;
            const __nv_bfloat16* src =
                (plane ? w_lo : w_hi) + (size_t)row * 256 + kb + c8;
            cp16(sb + GW(buf) + (plane ? 18432 : 0)
                 + (uint32_t)(row * RSA + c8) * 2, src);
        }
    };

    int rows[KF];
    if (GATHER == 0)      rows[0] = idx[m0 + r];
    else {
#pragma unroll
        for (int j = 0; j < KF; ++j) rows[j] = idx[(size_t)(m0 + r) * KF + j];
    }

    float v[16];
    auto PREF = [&](int ch) {
        const int kb = ch * 64;
        if (GATHER == 0) {
            const float4* p = (const float4*)(A + (size_t)rows[0] * 256 + kb + cq);
            float4 t0 = __ldg(p), t1 = __ldg(p + 1), t2 = __ldg(p + 2), t3 = __ldg(p + 3);
            v[0]  = t0.x; v[1]  = t0.y; v[2]  = t0.z; v[3]  = t0.w;
            v[4]  = t1.x; v[5]  = t1.y; v[6]  = t1.z; v[7]  = t1.w;
            v[8]  = t2.x; v[9]  = t2.y; v[10] = t2.z; v[11] = t2.w;
            v[12] = t3.x; v[13] = t3.y; v[14] = t3.z; v[15] = t3.w;
        } else {
#pragma unroll
            for (int i = 0; i < 16; ++i) v[i] = 0.f;
#pragma unroll
            for (int h = 0; h < 2; ++h) {
                float4 t[2 * KF];
#pragma unroll
                for (int j = 0; j < KF; ++j) {
                    const float4* p = (const float4*)(A + (size_t)rows[j] * 256
                                                      + kb + cq + h * 8);
                    t[j * 2]     = __ldg(p);
                    t[j * 2 + 1] = __ldg(p + 1);
                }
#pragma unroll
                for (int j = 0; j < KF; ++j)
#pragma unroll
                    for (int q = 0; q < 2; ++q) {
                        const float4 f = t[j * 2 + q];
                        const int o = h * 8 + q * 4;
                        v[o + 0] += f.x; v[o + 1] += f.y;
                        v[o + 2] += f.z; v[o + 3] += f.w;
                    }
            }
        }
    };
    auto STORE = [&](int buf) {
        const float s = 1.0f / (float)KF;
        float w[16];
#pragma unroll
        for (int i = 0; i < 16; ++i) w[i] = v[i] * s;
        uint4 h0, l0, h1, l1;
        split8(w, h0, l0);
        split8(w + 8, h1, l1);
        char* base = smem + GA(buf) + (size_t)(r * RSA + cq) * 2;
        *(uint4*)(base)              = h0;
        *(uint4*)(base + 16)         = h1;
        *(uint4*)(base + 9216)       = l0;
        *(uint4*)(base + 9216 + 16)  = l1;
    };

    float d[2][4][4];
#pragma unroll
    for (int i = 0; i < 2; ++i)
#pragma unroll
        for (int j = 0; j < 4; ++j)
#pragma unroll
            for (int k = 0; k < 4; ++k) d[i][j][k] = 0.f;

    ISSUE_W(0, 0);
    CP_COMMIT();
    PREF(0);
    STORE(0);
    CP_WAIT0();
    __syncthreads();

#pragma unroll
    for (int ch = 0; ch < 4; ++ch) {
        const int cb = ch & 1, nb = cb ^ 1;
        if (ch < 3) {
            ISSUE_W(ch + 1, nb);
            CP_COMMIT();
            PREF(ch + 1);
        }
        const uint32_t aH = sb + GA(cb), aL = aH + 9216;
        const uint32_t wH = sb + GW(cb), wL = wH + 18432;
#pragma unroll
        for (int ks = 0; ks < 4; ++ks) {
            uint32_t ah[2][4], al[2][4];
#pragma unroll
            for (int mi = 0; mi < 2; ++mi) {
                uint32_t ad = (uint32_t)((wm * 32 + mi * 16 + aro) * RSA
                                         + ks * 16 + aco) * 2;
                ldmx4(ah[mi], aH + ad);
                ldmx4(al[mi], aL + ad);
            }
            uint32_t bh[4][2], bl[4][2];
#pragma unroll
            for (int nip = 0; nip < 2; ++nip) {
                uint32_t bd = (uint32_t)((wn * 32 + nip * 16 + bro) * RSA
                                         + ks * 16 + bco) * 2;
                uint32_t t4[4];
                ldmx4(t4, wH + bd);
                bh[2 * nip][0] = t4[0]; bh[2 * nip][1] = t4[1];
                bh[2 * nip + 1][0] = t4[2]; bh[2 * nip + 1][1] = t4[3];
                ldmx4(t4, wL + bd);
                bl[2 * nip][0] = t4[0]; bl[2 * nip][1] = t4[1];
                bl[2 * nip + 1][0] = t4[2]; bl[2 * nip + 1][1] = t4[3];
            }
#pragma unroll
            for (int ni = 0; ni < 4; ++ni)
#pragma unroll
                for (int mi = 0; mi < 2; ++mi) {
                    mma16816(d[mi][ni], ah[mi], bh[ni][0], bh[ni][1]);
                    mma16816(d[mi][ni], ah[mi], bl[ni][0], bl[ni][1]);
                    mma16816(d[mi][ni], al[mi], bh[ni][0], bh[ni][1]);
                }
        }
        if (ch < 3) {
            STORE(nb);
            CP_WAIT0();
        }
        __syncthreads();
    }

#pragma unroll
    for (int mi = 0; mi < 2; ++mi) {
        const int row = m0 + wm * 32 + mi * 16 + lr;
#pragma unroll
        for (int ni = 0; ni < 4; ++ni) {
            const int col = wn * 32 + ni * 8 + lc;
            const float b0 = __ldg(&bias[col]), b1 = __ldg(&bias[col + 1]);
            *(float2*)(C + (size_t)row * ldc + col_off + col) =
                make_float2(fmaxf(d[mi][ni][0] + b0, 0.f),
                            fmaxf(d[mi][ni][1] + b1, 0.f));
            *(float2*)(C + (size_t)(row + 8) * ldc + col_off + col) =
                make_float2(fmaxf(d[mi][ni][2] + b0, 0.f),
                            fmaxf(d[mi][ni][3] + b1, 0.f));
        }
    }
}

// ---------------- layer 0: fused weight-split + 4 GEMM segments ------------------
__global__ void __launch_bounds__(256, 2)
layer0_k(const float* __restrict__ emb,
         const int* __restrict__ nodeids, const int* __restrict__ neigh1,
         const int* __restrict__ neigh2,
         const float* __restrict__ ws0, const float* __restrict__ wn0,
         const float* __restrict__ ws1, const float* __restrict__ wn1,
         const float* __restrict__ fcw,
         __nv_bfloat16* __restrict__ whi_o, __nv_bfloat16* __restrict__ wlo_o,
         const __nv_bfloat16* __restrict__ whi, const __nv_bfloat16* __restrict__ wlo,
         const float* __restrict__ bs0, const float* __restrict__ bn0,
         float* __restrict__ F0, float* __restrict__ F1)
{
    extern __shared__ char smem[];
    const int bid = blockIdx.x;
    const int tid = threadIdx.x;

    if (bid < 8) {
        const float* src[5] = {ws0, wn0, ws1, wn1, fcw};
#pragma unroll
        for (int i = 0; i < 20; ++i) {
            int idx4 = bid * 5120 + i * 256 + tid;
            int base = idx4 * 4;
            float4 f = __ldg((const float4*)(src[base >> 15] + (base & 32767)));
            uint32_t h0, l0, h1, l1;
            split2(f.x, f.y, h0, l0);
            split2(f.z, f.w, h1, l1);
            *(uint2*)(whi_o + base) = make_uint2(h0, h1);
            *(uint2*)(wlo_o + base) = make_uint2(l0, l1);
        }
        __syncthreads();
        if (tid == 0) {
            unsigned old;
            asm volatile("atom.add.release.gpu.u32 %0, [%1], 1;"
                         : "=r"(old) : "l"(&g_wflag) : "memory");
        }
    }
    if (tid == 0) {
        unsigned val;
        do {
            asm volatile("ld.acquire.gpu.u32 %0, [%1];"
                         : "=r"(val) : "l"(&g_wflag) : "memory");
            if (val >= 8u) break;
            __nanosleep(64);
        } while (true);
    }
    __syncthreads();

    if (bid < 768) {
        gemm_body<1, 5>(smem, emb, neigh2, whi + 32768, wlo + 32768, bn0,
                        F1, 256, 128, bid * 64);
    } else if (bid < 1536) {
        gemm_body<0, 1>(smem, emb, neigh1, whi, wlo, bs0,
                        F1, 256, 0, (bid - 768) * 64);
    } else if (bid < 1792) {
        gemm_body<1, 3>(smem, emb, neigh1, whi + 32768, wlo + 32768, bn0,
                        F0, 256, 128, (bid - 1536) * 64);
    } else {
        gemm_body<0, 1>(smem, emb, nodeids, whi, wlo, bs0,
                        F0, 256, 0, (bid - 1792) * 64);
    }
}

// ---------------- fused layer1 + L2-norm + FC, 256 thr, 2 CTAs/SM ----------------
__global__ void __launch_bounds__(256, 2)
l1fc_k(const float* __restrict__ F0, const float* __restrict__ F1,
       const __nv_bfloat16* __restrict__ w1_hi, const __nv_bfloat16* __restrict__ w1_lo,
       const float* __restrict__ bS, const float* __restrict__ bN,
       const __nv_bfloat16* __restrict__ fc_hi, const __nv_bfloat16* __restrict__ fc_lo,
       const float* __restrict__ fcb, float* __restrict__ out)
{
    extern __shared__ char smem[];
    const uint32_t sb = smem_u32(smem);
    const int tid = threadIdx.x, lane = tid & 31, wid = tid >> 5;
    const int wm = wid >> 2, wn = wid & 3;          // stage1: 2m x 4n, warp 32x64
    const int lr = lane >> 2, lc = (lane & 3) * 2;
    const int g  = lane >> 3, lm = lane & 7;
    const int aro = ((g & 1) << 3) + lm, aco = (g >> 1) << 3;
    const int bro = ((g >> 1) << 3) + lm, bco = (g & 1) << 3;
    const int m0 = blockIdx.x * 64;

    if (blockIdx.x == 0 && tid == 0) {
        asm volatile("st.relaxed.gpu.u32 [%0], 0;" :: "l"(&g_wflag) : "memory");
    }

    const bool isSelf = tid < 128;
    const int lt = tid & 127;
    const int r = lt >> 1, cq = (lt & 1) * 16;      // row 0..63, col base 0/16

    // per-k32-chunk W staging: 2048 cp16 / 256 thr = 8 each
    auto ISSUE_W = [&](int ch, int buf) {
        const int kb = ch * 32;
#pragma unroll
        for (int i = 0; i < 8; ++i) {
            int o = tid + i * 256;
            int plane = o >> 10, ix = o & 1023;
            int row = ix >> 2, c8 = (ix & 3) * 8;
            const __nv_bfloat16* src =
                (plane ? w1_lo : w1_hi) + (size_t)row * 256 + kb + c8;
            cp16(sb + C_W(buf) + (plane ? 20480 : 0)
                 + (uint32_t)(row * RSC + c8) * 2, src);
        }
    };

    float v[16];
    auto PREF = [&](int ch) {
        const int kb = ch * 32;
        if (isSelf) {
            const float4* p = (const float4*)(F0 + (size_t)(m0 + r) * 256 + kb + cq);
            float4 t0 = __ldg(p), t1 = __ldg(p + 1), t2 = __ldg(p + 2), t3 = __ldg(p + 3);
            v[0]  = t0.x; v[1]  = t0.y; v[2]  = t0.z; v[3]  = t0.w;
            v[4]  = t1.x; v[5]  = t1.y; v[6]  = t1.z; v[7]  = t1.w;
            v[8]  = t2.x; v[9]  = t2.y; v[10] = t2.z; v[11] = t2.w;
            v[12] = t3.x; v[13] = t3.y; v[14] = t3.z; v[15] = t3.w;
        } else {
            float4 t[12];                            // 12 independent LDGs
#pragma unroll
            for (int j = 0; j < 3; ++j) {
                const float4* p = (const float4*)(F1
                    + (size_t)((m0 + r) * 3 + j) * 256 + kb + cq);
#pragma unroll
                for (int q = 0; q < 4; ++q) t[j * 4 + q] = __ldg(p + q);
            }
#pragma unroll
            for (int i = 0; i < 16; ++i) v[i] = 0.f;
#pragma unroll
            for (int j = 0; j < 3; ++j)
#pragma unroll
                for (int q = 0; q < 4; ++q) {
                    const float4 f = t[j * 4 + q];
                    v[q * 4 + 0] += f.x; v[q * 4 + 1] += f.y;
                    v[q * 4 + 2] += f.z; v[q * 4 + 3] += f.w;
                }
#pragma unroll
            for (int i = 0; i < 16; ++i) v[i] *= (1.0f / 3.0f);
        }
    };
    auto STORE = [&]() {
        uint4 h0, l0, h1, l1;
        split8(v, h0, l0);
        split8(v + 8, h1, l1);
        char* base = smem + (isSelf ? C_ASH : C_ANH) + (size_t)(r * RSC + cq) * 2;
        *(uint4*)(base)             = h0;
        *(uint4*)(base + 16)        = h1;
        *(uint4*)(base + 5120)      = l0;
        *(uint4*)(base + 5120 + 16) = l1;
    };

    float d[2][8][4];
#pragma unroll
    for (int i = 0; i < 2; ++i)
#pragma unroll
        for (int j = 0; j < 8; ++j)
#pragma unroll
            for (int k = 0; k < 4; ++k) d[i][j][k] = 0.f;

    ISSUE_W(0, 0);
    CP_COMMIT();
    PREF(0);
    STORE();
    CP_WAIT0();
    __syncthreads();

    // stage 1: K=256 in 8 chunks of 32; A single-buffered, W double-buffered.
#pragma unroll
    for (int ch = 0; ch < 8; ++ch) {
        const int cb = ch & 1, nb = cb ^ 1;
        if (ch < 7) {
            ISSUE_W(ch + 1, nb);
            CP_COMMIT();
            PREF(ch + 1);            // LDGs fly under the MMA burst
        }
        const uint32_t aH = sb + (wn < 2 ? C_ASH : C_ANH);
        const uint32_t aL = aH + 5120;
        const uint32_t wH = sb + C_W(cb), wL = wH + 20480;
#pragma unroll
        for (int ks = 0; ks < 2; ++ks) {
            uint32_t ah[2][4], al[2][4];
#pragma unroll
            for (int mi = 0; mi < 2; ++mi) {
                uint32_t ad = (uint32_t)((wm * 32 + mi * 16 + aro) * RSC
                                         + ks * 16 + aco) * 2;
                ldmx4(ah[mi], aH + ad);
                ldmx4(al[mi], aL + ad);
            }
#pragma unroll
            for (int nip = 0; nip < 4; ++nip) {
                uint32_t bd = (uint32_t)((wn * 64 + nip * 16 + bro) * RSC
                                         + ks * 16 + bco) * 2;
                uint32_t th[4], tl[4];
                ldmx4(th, wH + bd);
                ldmx4(tl, wL + bd);
#pragma unroll
                for (int sub = 0; sub < 2; ++sub) {
                    const int ni = 2 * nip + sub;
#pragma unroll
                    for (int mi = 0; mi < 2; ++mi) {
                        mma16816(d[mi][ni], ah[mi], th[2 * sub], th[2 * sub + 1]);
                        mma16816(d[mi][ni], ah[mi], tl[2 * sub], tl[2 * sub + 1]);
                        mma16816(d[mi][ni], al[mi], th[2 * sub], th[2 * sub + 1]);
                    }
                }
            }
        }
        __syncthreads();             // all warps done reading A (single buf)
        if (ch < 7) {
            STORE();                  // refill A for chunk ch+1
            CP_WAIT0();               // W(ch+1) arrived (overlapped with MMA)
            __syncthreads();
        }
    }

    // ---- issue fc chunk 0 (into dead W region), hidden under epilogue --------
    auto ISSUE_FC = [&](int ch) {
        const int kb = ch * 64;
#pragma unroll
        for (int i = 0; i < 8; ++i) {
            int o = tid + i * 256;
            int plane = o >> 10, ix = o & 1023;
            int row = ix >> 3, c8 = (ix & 7) * 8;
            const __nv_bfloat16* src = (plane ? fc_lo : fc_hi)
                                     + (size_t)row * 256 + kb + c8;
            cp16(sb + C_FC + (plane ? 18432 : 0)
                 + (uint32_t)(row * RSA + c8) * 2, src);
        }
    };
    ISSUE_FC(0);
    CP_COMMIT();

    // ---- epilogue: bias + relu + row sum-of-squares --------------------------
    float* ss = (float*)(smem + C_SS);
    if (tid < 64) ss[tid] = 0.f;
    __syncthreads();

#pragma unroll
    for (int mi = 0; mi < 2; ++mi) {
        const int r0 = wm * 32 + mi * 16 + lr;
        float s0 = 0.f, s1 = 0.f;
#pragma unroll
        for (int ni = 0; ni < 8; ++ni) {
            const int col = wn * 64 + ni * 8 + lc;
            const float b0 = (col < 128) ? bS[col] : bN[col - 128];
            const float b1 = (col + 1 < 128) ? bS[col + 1] : bN[col - 127];
            d[mi][ni][0] = fmaxf(d[mi][ni][0] + b0, 0.f);
            d[mi][ni][1] = fmaxf(d[mi][ni][1] + b1, 0.f);
            d[mi][ni][2] = fmaxf(d[mi][ni][2] + b0, 0.f);
            d[mi][ni][3] = fmaxf(d[mi][ni][3] + b1, 0.f);
            s0 += d[mi][ni][0] * d[mi][ni][0] + d[mi][ni][1] * d[mi][ni][1];
            s1 += d[mi][ni][2] * d[mi][ni][2] + d[mi][ni][3] * d[mi][ni][3];
        }
        s0 += __shfl_xor_sync(0xffffffffu, s0, 1);
        s0 += __shfl_xor_sync(0xffffffffu, s0, 2);
        s1 += __shfl_xor_sync(0xffffffffu, s1, 1);
        s1 += __shfl_xor_sync(0xffffffffu, s1, 2);
        if ((lane & 3) == 0) {
            atomicAdd(&ss[r0], s0);
            atomicAdd(&ss[r0 + 8], s1);
        }
    }
    __syncthreads();

    // scale + split -> h planes (over dead stage-1 A/W region)
#pragma unroll
    for (int mi = 0; mi < 2; ++mi) {
        const int r0 = wm * 32 + mi * 16 + lr;
        const float sc0 = 1.0f / fmaxf(sqrtf(ss[r0]), 1e-12f);
        const float sc1 = 1.0f / fmaxf(sqrtf(ss[r0 + 8]), 1e-12f);
#pragma unroll
        for (int ni = 0; ni < 8; ++ni) {
            const int col = wn * 64 + ni * 8 + lc;
            uint32_t h, l;
            split2(d[mi][ni][0] * sc0, d[mi][ni][1] * sc0, h, l);
            *(uint32_t*)(smem + C_HH + (size_t)(r0 * RSH + col) * 2) = h;
            *(uint32_t*)(smem + C_HL + (size_t)(r0 * RSH + col) * 2) = l;
            split2(d[mi][ni][2] * sc1, d[mi][ni][3] * sc1, h, l);
            *(uint32_t*)(smem + C_HH + (size_t)((r0 + 8) * RSH + col) * 2) = h;
            *(uint32_t*)(smem + C_HL + (size_t)((r0 + 8) * RSH + col) * 2) = l;
        }
    }
    CP_WAIT0();
    __syncthreads();

    // ---- stage 2: out = h @ fc^T  (M=64, N=128, K=256, fc k64-chunked) -------
    float e[2][4][4];
#pragma unroll
    for (int i = 0; i < 2; ++i)
#pragma unroll
        for (int j = 0; j < 4; ++j)
#pragma unroll
            for (int k = 0; k < 4; ++k) e[i][j][k] = 0.f;

#pragma unroll
    for (int ch = 0; ch < 4; ++ch) {
        const int kb = ch * 64;
        const uint32_t fH = sb + C_FC, fL = fH + 18432;
#pragma unroll
        for (int ks = 0; ks < 4; ++ks) {
            uint32_t ah[2][4], al[2][4];
#pragma unroll
            for (int mi = 0; mi < 2; ++mi) {
                uint32_t ad = (uint32_t)((wm * 32 + mi * 16 + aro) * RSH
                                         + kb + ks * 16 + aco) * 2;
                ldmx4(ah[mi], sb + C_HH + ad);
                ldmx4(al[mi], sb + C_HL + ad);
            }
#pragma unroll
            for (int nip = 0; nip < 2; ++nip) {
                uint32_t bd = (uint32_t)((wn * 32 + nip * 16 + bro) * RSA
                                         + ks * 16 + bco) * 2;
                uint32_t th[4], tl[4];
                ldmx4(th, fH + bd);
                ldmx4(tl, fL + bd);
#pragma unroll
                for (int sub = 0; sub < 2; ++sub) {
                    const int ni = 2 * nip + sub;
#pragma unroll
                    for (int mi = 0; mi < 2; ++mi) {
                        mma16816(e[mi][ni], ah[mi], th[2 * sub], th[2 * sub + 1]);
                        mma16816(e[mi][ni], ah[mi], tl[2 * sub], tl[2 * sub + 1]);
                        mma16816(e[mi][ni], al[mi], th[2 * sub], th[2 * sub + 1]);
                    }
                }
            }
        }
        if (ch < 3) {
            __syncthreads();          // done reading fc buffer
            ISSUE_FC(ch + 1);
            CP_COMMIT();
            CP_WAIT0();
            __syncthreads();
        }
    }

    // final: + fc_b -> out
#pragma unroll
    for (int mi = 0; mi < 2; ++mi) {
        const int row = m0 + wm * 32 + mi * 16 + lr;
#pragma unroll
        for (int ni = 0; ni < 4; ++ni) {
            const int col = wn * 32 + ni * 8 + lc;
            const float b0 = __ldg(&fcb[col]), b1 = __ldg(&fcb[col + 1]);
            *(float2*)(out + (size_t)row * 128 + col) =
                make_float2(e[mi][ni][0] + b0, e[mi][ni][1] + b1);
            *(float2*)(out + (size_t)(row + 8) * 128 + col) =
                make_float2(e[mi][ni][2] + b0, e[mi][ni][3] + b1);
        }
    }
}

// ---------------------------------------------------------------------------
extern "C" void kernel_launch(void* const* d_in, const int* in_sizes, int n_in,
                              void* d_out, int out_size)
{
    const float* emb      = (const float*)d_in[0];
    const float* w_self0  = (const float*)d_in[1];
    const float* b_self0  = (const float*)d_in[2];
    const float* w_neigh0 = (const float*)d_in[3];
    const float* b_neigh0 = (const float*)d_in[4];
    const float* w_self1  = (const float*)d_in[5];
    const float* b_self1  = (const float*)d_in[6];
    const float* w_neigh1 = (const float*)d_in[7];
    const float* b_neigh1 = (const float*)d_in[8];
    const float* fc_w     = (const float*)d_in[9];
    const float* fc_b     = (const float*)d_in[10];
    const int*   nodeids  = (const int*)d_in[11];
    const int*   neigh1   = (const int*)d_in[12];
    const int*   neigh2   = (const int*)d_in[13];
    float*       out      = (float*)d_out;

    __nv_bfloat16 *WHI, *WLO;
    float *F0, *F1;
    cudaGetSymbolAddress((void**)&WHI, g_whi);
    cudaGetSymbolAddress((void**)&WLO, g_wlo);
    cudaGetSymbolAddress((void**)&F0, g_F0);
    cudaGetSymbolAddress((void**)&F1, g_F1);

    cudaFuncSetAttribute(layer0_k, cudaFuncAttributeMaxDynamicSharedMemorySize, G_SMEM);
    cudaFuncSetAttribute(l1fc_k,   cudaFuncAttributeMaxDynamicSharedMemorySize, L_SMEM);

    layer0_k<<<2048, 256, G_SMEM>>>(emb, nodeids, neigh1, neigh2,
                                    w_self0, w_neigh0, w_self1, w_neigh1, fc_w,
                                    WHI, WLO, WHI, WLO,
                                    b_self0, b_neigh0, F0, F1);

    l1fc_k<<<B_ROOT / 64, 256, L_SMEM>>>(F0, F1,
                                         WHI + 65536, WLO + 65536,
                                         b_self1, b_neigh1,
                                         WHI + 131072, WLO + 131072,
                                         fc_b, out);
}